// round 10
// baseline (speedup 1.0000x reference)
#include <cuda_runtime.h>
#include <cuda_fp16.h>
#include <cstdint>

#define D_IN   128
#define HID    512
#define D_OUTK 128
#define NOBJ   100000
#define NT     200000

#define BM 256
#define BN 128
#define BK 64                      // halfs per stage-chunk (128 B per row)
#define A_BYTES (BM * BK * 2)      // 32 KB
#define B_BYTES (BN * BK * 2)      // 16 KB
#define STAGE_BYTES (A_BYTES + B_BYTES)  // 48 KB
#define NSTAGE 3
#define SMEMB (NSTAGE * STAGE_BYTES)     // 144 KB
#define NTHREADS 256

// Scratch (device globals — no allocation allowed)
__device__ __align__(16) __half g_h[(size_t)NT * HID];
__device__ __align__(16) float  g_pooled[(size_t)NOBJ * HID];
__device__ __align__(16) __half g_pooledh[(size_t)NOBJ * HID];
__device__ __align__(16) __half g_tmph[(size_t)NOBJ * HID];
__device__ __align__(16) float  g_counts[NOBJ];
__device__ __align__(16) __half g_objth[(size_t)NOBJ * D_IN];
__device__ __align__(16) __half g_predth[(size_t)NT * D_IN];
// Weights transposed to [n][k], fp16
__device__ __align__(16) __half g_W1T[(size_t)HID * 384];
__device__ __align__(16) __half g_W2T[(size_t)1152 * HID];
__device__ __align__(16) __half g_W3T[(size_t)HID * HID];
__device__ __align__(16) __half g_W4T[(size_t)D_OUTK * HID];

// ---------------------------------------------------------------------------
__device__ __forceinline__ void mma_f16(float* c, const uint32_t* a, const uint32_t* b) {
    asm volatile(
        "mma.sync.aligned.m16n8k16.row.col.f32.f16.f16.f32 "
        "{%0,%1,%2,%3}, {%4,%5,%6,%7}, {%8,%9}, {%0,%1,%2,%3};"
        : "+f"(c[0]), "+f"(c[1]), "+f"(c[2]), "+f"(c[3])
        : "r"(a[0]), "r"(a[1]), "r"(a[2]), "r"(a[3]), "r"(b[0]), "r"(b[1]));
}

__device__ __forceinline__ void ldsm4(uint32_t& r0, uint32_t& r1, uint32_t& r2,
                                      uint32_t& r3, uint32_t addr) {
    asm volatile("ldmatrix.sync.aligned.m8n8.x4.shared.b16 {%0,%1,%2,%3}, [%4];"
                 : "=r"(r0), "=r"(r1), "=r"(r2), "=r"(r3) : "r"(addr));
}

__device__ __forceinline__ void cp16(uint32_t d, const void* s, int sz) {
    asm volatile("cp.async.cg.shared.global [%0], [%1], 16, %2;"
                 :: "r"(d), "l"(s), "r"(sz));
}
#define CP_COMMIT() asm volatile("cp.async.commit_group;" ::: "memory")
#define CP_WAIT1()  asm volatile("cp.async.wait_group 1;" ::: "memory")

__device__ __forceinline__ void red_add_v2(float* addr, float x, float y) {
    asm volatile("red.global.add.v2.f32 [%0], {%1, %2};"
                 :: "l"(addr), "f"(x), "f"(y) : "memory");
}

// ---------------------------------------------------------------------------
__global__ void zero_counts() {
    int i = blockIdx.x * blockDim.x + threadIdx.x;
    if (i < NOBJ) g_counts[i] = 0.f;
}

// Section-dispatched prep: pooled zero | cvt obj | cvt pred | cvtT W1-4 | count
#define NB_POOL  50000
#define NB_OBJ   12500
#define NB_PRED  25000
#define NB_W1    768
#define NB_W2    2304
#define NB_W3    1024
#define NB_W4    256
#define NB_CNT   782
#define NB_TOTAL (NB_POOL + NB_OBJ + NB_PRED + NB_W1 + NB_W2 + NB_W3 + NB_W4 + NB_CNT)

__device__ __forceinline__ void cvt_sec(const float* src, __half* dst, int i) {
    float4 v = ((const float4*)src)[i];
    __half2* d2 = (__half2*)dst;
    d2[2 * i]     = __floats2half2_rn(v.x, v.y);
    d2[2 * i + 1] = __floats2half2_rn(v.z, v.w);
}
__device__ __forceinline__ void cvtT_sec(const float* W, __half* WT, int K, int N, int idx) {
    int n = idx / K, k = idx - n * K;
    WT[idx] = __float2half_rn(W[(size_t)k * N + n]);
}

__global__ void prep_kernel(const float* __restrict__ obj, const float* __restrict__ pred,
                            const int* __restrict__ edges,
                            const float* __restrict__ W1, const float* __restrict__ W2,
                            const float* __restrict__ W3, const float* __restrict__ W4)
{
    int b = blockIdx.x;
    int t = threadIdx.x;
    if (b < NB_POOL) {
        int i = b * 256 + t;
        ((float4*)g_pooled)[i] = make_float4(0.f, 0.f, 0.f, 0.f);
        return;
    }
    b -= NB_POOL;
    if (b < NB_OBJ)  { cvt_sec(obj,  g_objth,  b * 256 + t); return; }
    b -= NB_OBJ;
    if (b < NB_PRED) { cvt_sec(pred, g_predth, b * 256 + t); return; }
    b -= NB_PRED;
    if (b < NB_W1) { cvtT_sec(W1, g_W1T, 384, 512,  b * 256 + t); return; }
    b -= NB_W1;
    if (b < NB_W2) { cvtT_sec(W2, g_W2T, 512, 1152, b * 256 + t); return; }
    b -= NB_W2;
    if (b < NB_W3) { cvtT_sec(W3, g_W3T, 512, 512,  b * 256 + t); return; }
    b -= NB_W3;
    if (b < NB_W4) { cvtT_sec(W4, g_W4T, 512, 128,  b * 256 + t); return; }
    b -= NB_W4;
    {
        int e = b * 256 + t;
        if (e < NT) {
            atomicAdd(&g_counts[edges[2 * e]],     1.f);
            atomicAdd(&g_counts[edges[2 * e + 1]], 1.f);
        }
    }
}

__global__ void normalize_h() {
    int i = blockIdx.x * blockDim.x + threadIdx.x;
    if (i < (NOBJ * HID) / 4) {
        int r = i >> 7;
        float sc = 1.f / fmaxf(g_counts[r], 1.f);
        float4 v = ((const float4*)g_pooled)[i];
        __half2* d2 = (__half2*)g_pooledh;
        d2[2 * i]     = __floats2half2_rn(v.x * sc, v.y * sc);
        d2[2 * i + 1] = __floats2half2_rn(v.z * sc, v.w * sc);
    }
}

// ---------------------------------------------------------------------------
// 256 threads = 8 warps in 4(m) x 2(n); warp tile 64x64; CTA tile 256x128.
// KIND 0: g_h    = h(relu(gather @ W1T + b1))        M=NT,   K=384, N=512
// KIND 1: scatter/out_p from relu(g_h @ W2T + b2)    M=NT,   K=512, N=1152
// KIND 2: g_tmph = h(relu(pooledh @ W3T + b3))       M=NOBJ, K=512, N=512
// KIND 3: out_obj = relu(g_tmph @ W4T + b4)          M=NOBJ, K=512, N=128
template<int KIND>
__global__ void __launch_bounds__(NTHREADS, 1) hgemm(const int* __restrict__ edges,
                                                     const float* __restrict__ bias,
                                                     float* __restrict__ out, int M)
{
    constexpr int K  = (KIND == 0) ? 384 : 512;
    constexpr int KT = K / BK;
    extern __shared__ __align__(16) char sh[];
    uint32_t sm = (uint32_t)__cvta_generic_to_shared(sh);

    int tid = threadIdx.x, lane = tid & 31, w = tid >> 5;
    int wm = w & 3, wn = w >> 2;                 // 4 (m) x 2 (n) warps
    int gr = lane >> 2, ct = lane & 3;
    int sel = lane >> 3, lr = lane & 7;          // ldmatrix lane roles
    int row0 = blockIdx.y * BM;
    int col0 = blockIdx.x * BN;

    int mode = 0, pcol = 0;                      // KIND 1 column routing
    if (KIND == 1) {
        int bx = blockIdx.x;
        if (bx < 4)       { mode = 0; pcol = bx * 128; }
        else if (bx == 4) { mode = 1; pcol = 0; }
        else              { mode = 2; pcol = (bx - 5) * 128; }
    }

    const __half* Wt   = (KIND == 0) ? g_W1T : (KIND == 1) ? g_W2T
                       : (KIND == 2) ? g_W3T : g_W4T;
    const __half* Amat = (KIND == 1) ? g_h : (KIND == 2) ? g_pooledh : g_tmph;

    float acc[4][8][4];
#pragma unroll
    for (int i = 0; i < 4; i++)
#pragma unroll
        for (int j = 0; j < 8; j++)
#pragma unroll
            for (int k = 0; k < 4; k++) acc[i][j][k] = 0.f;

    auto load_stage = [&](int kt) {
        int k0 = kt * BK;                          // in halfs
        uint32_t ab = sm + (uint32_t)(kt % NSTAGE) * STAGE_BYTES;
        uint32_t bb = ab + A_BYTES;
#pragma unroll
        for (int i = 0; i < 8; i++) {              // A: 256 rows x 8 chunks
            int f = tid + i * NTHREADS;
            int m = f >> 3, ch = f & 7;
            int mg = row0 + m;
            int sz = (mg < M) ? 16 : 0;
            int mc = (mg < M) ? mg : M - 1;
            const char* src;
            if (KIND == 0) {
                int region = k0 >> 7;
                int bo = (k0 & 127) * 2;
                if (region == 0)      src = (const char*)(g_objth  + (size_t)edges[2 * mc]     * 128) + bo;
                else if (region == 1) src = (const char*)(g_predth + (size_t)mc                * 128) + bo;
                else                  src = (const char*)(g_objth  + (size_t)edges[2 * mc + 1] * 128) + bo;
            } else {
                src = (const char*)(Amat + (size_t)mc * K + k0);
            }
            cp16(ab + (uint32_t)(m * 128 + ((ch ^ (m & 7)) * 16)), src + ch * 16, sz);
        }
#pragma unroll
        for (int i = 0; i < 4; i++) {              // B: 128 n-rows x 8 chunks
            int f = tid + i * NTHREADS;
            int n = f >> 3, ch = f & 7;
            const char* src = (const char*)(Wt + (size_t)(col0 + n) * K + k0) + ch * 16;
            cp16(bb + (uint32_t)(n * 128 + ((ch ^ (n & 7)) * 16)), src, 16);
        }
    };

    int a_row[4];
#pragma unroll
    for (int mf = 0; mf < 4; mf++)
        a_row[mf] = wm * 64 + mf * 16 + lr + ((sel & 1) << 3);
    int b_row[4];
#pragma unroll
    for (int p = 0; p < 4; p++)
        b_row[p] = wn * 64 + p * 16 + lr + ((sel >> 1) << 3);

    auto mma_stage = [&](int b) {
        uint32_t abase = sm + (uint32_t)b * STAGE_BYTES;
        uint32_t bbase = abase + A_BYTES;
#pragma unroll
        for (int kb = 0; kb < BK / 16; kb++) {
            uint32_t a[4][4], bf[8][2];
            int a_ch = 2 * kb + (sel >> 1);
#pragma unroll
            for (int mf = 0; mf < 4; mf++) {
                int r = a_row[mf];
                uint32_t addr = abase + (uint32_t)(r * 128 + ((a_ch ^ (r & 7)) * 16));
                ldsm4(a[mf][0], a[mf][1], a[mf][2], a[mf][3], addr);
            }
            int b_ch = 2 * kb + (sel & 1);
#pragma unroll
            for (int p = 0; p < 4; p++) {
                int r = b_row[p];
                uint32_t addr = bbase + (uint32_t)(r * 128 + ((b_ch ^ (r & 7)) * 16));
                ldsm4(bf[2 * p][0], bf[2 * p][1], bf[2 * p + 1][0], bf[2 * p + 1][1], addr);
            }
#pragma unroll
            for (int mf = 0; mf < 4; mf++)
#pragma unroll
                for (int nf = 0; nf < 8; nf++)
                    mma_f16(acc[mf][nf], a[mf], bf[nf]);
        }
    };

    load_stage(0); CP_COMMIT();
    load_stage(1); CP_COMMIT();

    for (int kt = 0; kt < KT; kt++) {
        CP_WAIT1();
        __syncthreads();
        if (kt + 2 < KT) load_stage(kt + 2);
        CP_COMMIT();
        mma_stage(kt % NSTAGE);
    }

    // ---- epilogue ----
    float bb[8][2];
#pragma unroll
    for (int nf = 0; nf < 8; nf++) {
        int c = col0 + wn * 64 + nf * 8 + ct * 2;
        bb[nf][0] = bias[c]; bb[nf][1] = bias[c + 1];
    }

#pragma unroll
    for (int mf = 0; mf < 4; mf++)
#pragma unroll
        for (int half = 0; half < 2; half++) {
            int r = row0 + wm * 64 + mf * 16 + gr + half * 8;
            if (r >= M) continue;
            int cbase = wn * 64 + ct * 2;
            if (KIND == 0 || KIND == 2) {
                __half* dst = ((KIND == 0) ? g_h : g_tmph) + (size_t)r * HID + col0 + cbase;
#pragma unroll
                for (int nf = 0; nf < 8; nf++) {
                    float x = fmaxf(acc[mf][nf][half * 2 + 0] + bb[nf][0], 0.f);
                    float y = fmaxf(acc[mf][nf][half * 2 + 1] + bb[nf][1], 0.f);
                    *(__half2*)(dst + nf * 8) = __floats2half2_rn(x, y);
                }
            } else if (KIND == 3) {
                float* dst = out + (size_t)r * D_OUTK + cbase;
#pragma unroll
                for (int nf = 0; nf < 8; nf++) {
                    float2 o;
                    o.x = fmaxf(acc[mf][nf][half * 2 + 0] + bb[nf][0], 0.f);
                    o.y = fmaxf(acc[mf][nf][half * 2 + 1] + bb[nf][1], 0.f);
                    *(float2*)(dst + nf * 8) = o;
                }
            } else {  // KIND == 1
                if (mode == 1) {
                    float* dst = out + (size_t)r * D_OUTK + cbase;
#pragma unroll
                    for (int nf = 0; nf < 8; nf++) {
                        float2 o;
                        o.x = fmaxf(acc[mf][nf][half * 2 + 0] + bb[nf][0], 0.f);
                        o.y = fmaxf(acc[mf][nf][half * 2 + 1] + bb[nf][1], 0.f);
                        *(float2*)(dst + nf * 8) = o;
                    }
                } else {
                    int sidx = (mode == 0) ? edges[2 * r] : edges[2 * r + 1];
                    float* dst = g_pooled + (size_t)sidx * HID + pcol + cbase;
#pragma unroll
                    for (int nf = 0; nf < 8; nf++) {
                        float x = fmaxf(acc[mf][nf][half * 2 + 0] + bb[nf][0], 0.f);
                        float y = fmaxf(acc[mf][nf][half * 2 + 1] + bb[nf][1], 0.f);
                        red_add_v2(dst + nf * 8, x, y);
                    }
                }
            }
        }
}

// ---------------------------------------------------------------------------
extern "C" void kernel_launch(void* const* d_in, const int* in_sizes, int n_in,
                              void* d_out, int out_size)
{
    const float* obj   = (const float*)d_in[0];
    const float* pred  = (const float*)d_in[1];
    const int*   edges = (const int*)  d_in[2];
    const float* W1 = (const float*)d_in[3];
    const float* b1 = (const float*)d_in[4];
    const float* W2 = (const float*)d_in[5];
    const float* b2 = (const float*)d_in[6];
    const float* W3 = (const float*)d_in[7];
    const float* b3 = (const float*)d_in[8];
    const float* W4 = (const float*)d_in[9];
    const float* b4 = (const float*)d_in[10];

    float* out     = (float*)d_out;
    float* out_obj = out;                           // (NOBJ, 128)
    float* out_p   = out + (size_t)NOBJ * D_OUTK;   // (NT, 128)

    cudaFuncSetAttribute(hgemm<0>, cudaFuncAttributeMaxDynamicSharedMemorySize, SMEMB);
    cudaFuncSetAttribute(hgemm<1>, cudaFuncAttributeMaxDynamicSharedMemorySize, SMEMB);
    cudaFuncSetAttribute(hgemm<2>, cudaFuncAttributeMaxDynamicSharedMemorySize, SMEMB);
    cudaFuncSetAttribute(hgemm<3>, cudaFuncAttributeMaxDynamicSharedMemorySize, SMEMB);

    zero_counts<<<(NOBJ + 255) / 256, 256>>>();
    prep_kernel<<<NB_TOTAL, 256>>>(obj, pred, edges, W1, W2, W3, W4);

    int gy_t = (NT + BM - 1) / BM;    // 782
    int gy_o = (NOBJ + BM - 1) / BM;  // 391

    hgemm<0><<<dim3(4, gy_t), NTHREADS, SMEMB>>>(edges, b1, nullptr, NT);
    hgemm<1><<<dim3(9, gy_t), NTHREADS, SMEMB>>>(edges, b2, out_p, NT);
    normalize_h<<<(NOBJ * HID / 4 + 255) / 256, 256>>>();
    hgemm<2><<<dim3(4, gy_o), NTHREADS, SMEMB>>>(edges, b3, nullptr, NOBJ);
    hgemm<3><<<dim3(1, gy_o), NTHREADS, SMEMB>>>(edges, b4, out_obj, NOBJ);
}

// round 11
// speedup vs baseline: 1.1610x; 1.1610x over previous
#include <cuda_runtime.h>
#include <cuda_fp16.h>
#include <cstdint>

#define D_IN   128
#define HID    512
#define D_OUTK 128
#define NOBJ   100000
#define NT     200000

#define BM 128
#define BN 128
#define BK 64                      // halfs per stage-chunk (128 B per row)
#define A_BYTES (BM * BK * 2)      // 16 KB
#define STAGE_BYTES (2 * A_BYTES)  // A + B = 32 KB
#define NSTAGE 3
#define SMEMB (NSTAGE * STAGE_BYTES)

// Scratch (device globals — no allocation allowed)
__device__ __align__(16) __half g_h[(size_t)NT * HID];
__device__ __align__(16) float  g_pooled[(size_t)NOBJ * HID];
__device__ __align__(16) __half g_pooledh[(size_t)NOBJ * HID];
__device__ __align__(16) __half g_tmph[(size_t)NOBJ * HID];
__device__ __align__(16) float  g_counts[NOBJ];
__device__ __align__(16) __half g_objth[(size_t)NOBJ * D_IN];
__device__ __align__(16) __half g_predth[(size_t)NT * D_IN];
// Weights transposed to [n][k], fp16
__device__ __align__(16) __half g_W1T[(size_t)HID * 384];
__device__ __align__(16) __half g_W2T[(size_t)1152 * HID];
__device__ __align__(16) __half g_W3T[(size_t)HID * HID];
__device__ __align__(16) __half g_W4T[(size_t)D_OUTK * HID];

// ---------------------------------------------------------------------------
__device__ __forceinline__ void mma_f16(float* c, const uint32_t* a, const uint32_t* b) {
    asm volatile(
        "mma.sync.aligned.m16n8k16.row.col.f32.f16.f16.f32 "
        "{%0,%1,%2,%3}, {%4,%5,%6,%7}, {%8,%9}, {%0,%1,%2,%3};"
        : "+f"(c[0]), "+f"(c[1]), "+f"(c[2]), "+f"(c[3])
        : "r"(a[0]), "r"(a[1]), "r"(a[2]), "r"(a[3]), "r"(b[0]), "r"(b[1]));
}

__device__ __forceinline__ void ldsm4(uint32_t& r0, uint32_t& r1, uint32_t& r2,
                                      uint32_t& r3, uint32_t addr) {
    asm volatile("ldmatrix.sync.aligned.m8n8.x4.shared.b16 {%0,%1,%2,%3}, [%4];"
                 : "=r"(r0), "=r"(r1), "=r"(r2), "=r"(r3) : "r"(addr));
}

__device__ __forceinline__ void cp16(uint32_t d, const void* s, int sz) {
    asm volatile("cp.async.cg.shared.global [%0], [%1], 16, %2;"
                 :: "r"(d), "l"(s), "r"(sz));
}
#define CP_COMMIT() asm volatile("cp.async.commit_group;" ::: "memory")
#define CP_WAIT1()  asm volatile("cp.async.wait_group 1;" ::: "memory")

__device__ __forceinline__ void red_add_v4(float* addr, float a, float b,
                                           float c, float d) {
    asm volatile("red.global.add.v4.f32 [%0], {%1, %2, %3, %4};"
                 :: "l"(addr), "f"(a), "f"(b), "f"(c), "f"(d) : "memory");
}

// ---------------------------------------------------------------------------
__global__ void zero_counts() {
    int i = blockIdx.x * blockDim.x + threadIdx.x;
    if (i < NOBJ) g_counts[i] = 0.f;
}

// Section-dispatched prep: pooled zero | cvt obj | cvt pred | cvtT W1-4 | count
#define NB_POOL  50000
#define NB_OBJ   12500
#define NB_PRED  25000
#define NB_W1    768
#define NB_W2    2304
#define NB_W3    1024
#define NB_W4    256
#define NB_CNT   782
#define NB_TOTAL (NB_POOL + NB_OBJ + NB_PRED + NB_W1 + NB_W2 + NB_W3 + NB_W4 + NB_CNT)

__device__ __forceinline__ void cvt_sec(const float* src, __half* dst, int i) {
    float4 v = ((const float4*)src)[i];
    __half2* d2 = (__half2*)dst;
    d2[2 * i]     = __floats2half2_rn(v.x, v.y);
    d2[2 * i + 1] = __floats2half2_rn(v.z, v.w);
}
__device__ __forceinline__ void cvtT_sec(const float* W, __half* WT, int K, int N, int idx) {
    int n = idx / K, k = idx - n * K;
    WT[idx] = __float2half_rn(W[(size_t)k * N + n]);
}

__global__ void prep_kernel(const float* __restrict__ obj, const float* __restrict__ pred,
                            const int* __restrict__ edges,
                            const float* __restrict__ W1, const float* __restrict__ W2,
                            const float* __restrict__ W3, const float* __restrict__ W4)
{
    int b = blockIdx.x;
    int t = threadIdx.x;
    if (b < NB_POOL) {
        int i = b * 256 + t;
        ((float4*)g_pooled)[i] = make_float4(0.f, 0.f, 0.f, 0.f);
        return;
    }
    b -= NB_POOL;
    if (b < NB_OBJ)  { cvt_sec(obj,  g_objth,  b * 256 + t); return; }
    b -= NB_OBJ;
    if (b < NB_PRED) { cvt_sec(pred, g_predth, b * 256 + t); return; }
    b -= NB_PRED;
    if (b < NB_W1) { cvtT_sec(W1, g_W1T, 384, 512,  b * 256 + t); return; }
    b -= NB_W1;
    if (b < NB_W2) { cvtT_sec(W2, g_W2T, 512, 1152, b * 256 + t); return; }
    b -= NB_W2;
    if (b < NB_W3) { cvtT_sec(W3, g_W3T, 512, 512,  b * 256 + t); return; }
    b -= NB_W3;
    if (b < NB_W4) { cvtT_sec(W4, g_W4T, 512, 128,  b * 256 + t); return; }
    b -= NB_W4;
    {
        int e = b * 256 + t;
        if (e < NT) {
            atomicAdd(&g_counts[edges[2 * e]],     1.f);
            atomicAdd(&g_counts[edges[2 * e + 1]], 1.f);
        }
    }
}

__global__ void normalize_h() {
    int i = blockIdx.x * blockDim.x + threadIdx.x;
    if (i < (NOBJ * HID) / 4) {
        int r = i >> 7;
        float sc = 1.f / fmaxf(g_counts[r], 1.f);
        float4 v = ((const float4*)g_pooled)[i];
        __half2* d2 = (__half2*)g_pooledh;
        d2[2 * i]     = __floats2half2_rn(v.x * sc, v.y * sc);
        d2[2 * i + 1] = __floats2half2_rn(v.z * sc, v.w * sc);
    }
}

// ---------------------------------------------------------------------------
// 256 threads = 8 warps in 4(m) x 2(n); warp tile 32x64; CTA tile 128x128.
// KIND 0: g_h    = h(relu(gather @ W1T + b1))        M=NT,   K=384, N=512
// KIND 1: scatter/out_p from relu(g_h @ W2T + b2)    M=NT,   K=512, N=1152
// KIND 2: g_tmph = h(relu(pooledh @ W3T + b3))       M=NOBJ, K=512, N=512
// KIND 3: out_obj = relu(g_tmph @ W4T + b4)          M=NOBJ, K=512, N=128
template<int KIND>
__global__ void __launch_bounds__(256, 2) hgemm(const int* __restrict__ edges,
                                                const float* __restrict__ bias,
                                                float* __restrict__ out, int M)
{
    constexpr int K  = (KIND == 0) ? 384 : 512;
    constexpr int KT = K / BK;
    extern __shared__ __align__(16) char sh[];
    uint32_t sm = (uint32_t)__cvta_generic_to_shared(sh);

    int tid = threadIdx.x, lane = tid & 31, w = tid >> 5;
    int wm = w & 3, wn = w >> 2;                 // 4 (m) x 2 (n) warps
    int gr = lane >> 2, ct = lane & 3;
    int sel = lane >> 3, lr = lane & 7;          // ldmatrix lane roles
    int row0 = blockIdx.y * BM;
    int col0 = blockIdx.x * BN;

    int mode = 0, pcol = 0;                      // KIND 1 column routing
    if (KIND == 1) {
        int bx = blockIdx.x;
        if (bx < 4)       { mode = 0; pcol = bx * 128; }
        else if (bx == 4) { mode = 1; pcol = 0; }
        else              { mode = 2; pcol = (bx - 5) * 128; }
    }

    const __half* Wt   = (KIND == 0) ? g_W1T : (KIND == 1) ? g_W2T
                       : (KIND == 2) ? g_W3T : g_W4T;
    const __half* Amat = (KIND == 1) ? g_h : (KIND == 2) ? g_pooledh : g_tmph;

    float acc[2][8][4];
#pragma unroll
    for (int i = 0; i < 2; i++)
#pragma unroll
        for (int j = 0; j < 8; j++)
#pragma unroll
            for (int k = 0; k < 4; k++) acc[i][j][k] = 0.f;

    auto load_stage = [&](int kt) {
        int k0 = kt * BK;                          // in halfs
        uint32_t ab = sm + (uint32_t)(kt % NSTAGE) * STAGE_BYTES;
        uint32_t bb = ab + A_BYTES;
#pragma unroll
        for (int i = 0; i < 4; i++) {              // A: 128 rows x 8 chunks
            int f = tid + i * 256;
            int m = f >> 3, ch = f & 7;
            int mg = row0 + m;
            int sz = (mg < M) ? 16 : 0;
            int mc = (mg < M) ? mg : M - 1;
            const char* src;
            if (KIND == 0) {
                int region = k0 >> 7;
                int bo = (k0 & 127) * 2;
                if (region == 0)      src = (const char*)(g_objth  + (size_t)edges[2 * mc]     * 128) + bo;
                else if (region == 1) src = (const char*)(g_predth + (size_t)mc                * 128) + bo;
                else                  src = (const char*)(g_objth  + (size_t)edges[2 * mc + 1] * 128) + bo;
            } else {
                src = (const char*)(Amat + (size_t)mc * K + k0);
            }
            cp16(ab + (uint32_t)(m * 128 + ((ch ^ (m & 7)) * 16)), src + ch * 16, sz);
        }
#pragma unroll
        for (int i = 0; i < 4; i++) {              // B: 128 n-rows x 8 chunks
            int f = tid + i * 256;
            int n = f >> 3, ch = f & 7;
            const char* src = (const char*)(Wt + (size_t)(col0 + n) * K + k0) + ch * 16;
            cp16(bb + (uint32_t)(n * 128 + ((ch ^ (n & 7)) * 16)), src, 16);
        }
    };

    int a_row[2];
#pragma unroll
    for (int mf = 0; mf < 2; mf++)
        a_row[mf] = wm * 32 + mf * 16 + lr + ((sel & 1) << 3);
    int b_row[4];
#pragma unroll
    for (int p = 0; p < 4; p++)
        b_row[p] = wn * 64 + p * 16 + lr + ((sel >> 1) << 3);

    auto mma_stage = [&](int b) {
        uint32_t abase = sm + (uint32_t)b * STAGE_BYTES;
        uint32_t bbase = abase + A_BYTES;
#pragma unroll
        for (int kb = 0; kb < BK / 16; kb++) {
            uint32_t a[2][4], bf[8][2];
            int a_ch = 2 * kb + (sel >> 1);
#pragma unroll
            for (int mf = 0; mf < 2; mf++) {
                int r = a_row[mf];
                uint32_t addr = abase + (uint32_t)(r * 128 + ((a_ch ^ (r & 7)) * 16));
                ldsm4(a[mf][0], a[mf][1], a[mf][2], a[mf][3], addr);
            }
            int b_ch = 2 * kb + (sel & 1);
#pragma unroll
            for (int p = 0; p < 4; p++) {
                int r = b_row[p];
                uint32_t addr = bbase + (uint32_t)(r * 128 + ((b_ch ^ (r & 7)) * 16));
                ldsm4(bf[2 * p][0], bf[2 * p][1], bf[2 * p + 1][0], bf[2 * p + 1][1], addr);
            }
#pragma unroll
            for (int mf = 0; mf < 2; mf++)
#pragma unroll
                for (int nf = 0; nf < 8; nf++)
                    mma_f16(acc[mf][nf], a[mf], bf[nf]);
        }
    };

    load_stage(0); CP_COMMIT();
    load_stage(1); CP_COMMIT();

    for (int kt = 0; kt < KT; kt++) {
        CP_WAIT1();
        __syncthreads();
        if (kt + 2 < KT) load_stage(kt + 2);
        CP_COMMIT();
        mma_stage(kt % NSTAGE);
    }

    // ---- epilogue ----
    float bb[8][2];
#pragma unroll
    for (int nf = 0; nf < 8; nf++) {
        int c = col0 + wn * 64 + nf * 8 + ct * 2;
        bb[nf][0] = bias[c]; bb[nf][1] = bias[c + 1];
    }

    if (KIND == 1 && mode != 1) {
        // Shuffle-paired v4 scatter: even ct lane reds row r, odd ct reds row r+8,
        // each covering 4 contiguous columns (16B aligned).
        int halfsel = ct & 1;
        int q = ct >> 1;
#pragma unroll
        for (int mf = 0; mf < 2; mf++) {
            int rbase = row0 + wm * 32 + mf * 16 + gr;
            int myrow = rbase + (halfsel ? 8 : 0);
            bool valid = myrow < M;
            int sidx = 0;
            if (valid) sidx = (mode == 0) ? edges[2 * myrow] : edges[2 * myrow + 1];
            float* dstrow = g_pooled + (size_t)sidx * HID + pcol + wn * 64 + q * 4;
#pragma unroll
            for (int nf = 0; nf < 8; nf++) {
                float v0 = fmaxf(acc[mf][nf][0] + bb[nf][0], 0.f);  // row r,   col c
                float v1 = fmaxf(acc[mf][nf][1] + bb[nf][1], 0.f);  // row r,   col c+1
                float v2 = fmaxf(acc[mf][nf][2] + bb[nf][0], 0.f);  // row r+8, col c
                float v3 = fmaxf(acc[mf][nf][3] + bb[nf][1], 0.f);  // row r+8, col c+1
                float s0 = halfsel ? v0 : v2;
                float s1 = halfsel ? v1 : v3;
                float p0 = __shfl_xor_sync(0xffffffffu, s0, 1);
                float p1 = __shfl_xor_sync(0xffffffffu, s1, 1);
                float o0 = halfsel ? p0 : v0;
                float o1 = halfsel ? p1 : v1;
                float o2 = halfsel ? v2 : p0;
                float o3 = halfsel ? v3 : p1;
                if (valid) red_add_v4(dstrow + nf * 8, o0, o1, o2, o3);
            }
        }
    } else {
#pragma unroll
        for (int mf = 0; mf < 2; mf++)
#pragma unroll
            for (int half = 0; half < 2; half++) {
                int r = row0 + wm * 32 + mf * 16 + gr + half * 8;
                if (r >= M) continue;
                int cbase = wn * 64 + ct * 2;
                if (KIND == 0 || KIND == 2) {
                    __half* dst = ((KIND == 0) ? g_h : g_tmph) + (size_t)r * HID + col0 + cbase;
#pragma unroll
                    for (int nf = 0; nf < 8; nf++) {
                        float x = fmaxf(acc[mf][nf][half * 2 + 0] + bb[nf][0], 0.f);
                        float y = fmaxf(acc[mf][nf][half * 2 + 1] + bb[nf][1], 0.f);
                        *(__half2*)(dst + nf * 8) = __floats2half2_rn(x, y);
                    }
                } else {  // KIND 3 or KIND 1 mode==1: contiguous float stores
                    float* dst = out + (size_t)r * D_OUTK + cbase;
#pragma unroll
                    for (int nf = 0; nf < 8; nf++) {
                        float2 o;
                        o.x = fmaxf(acc[mf][nf][half * 2 + 0] + bb[nf][0], 0.f);
                        o.y = fmaxf(acc[mf][nf][half * 2 + 1] + bb[nf][1], 0.f);
                        *(float2*)(dst + nf * 8) = o;
                    }
                }
            }
    }
}

// ---------------------------------------------------------------------------
extern "C" void kernel_launch(void* const* d_in, const int* in_sizes, int n_in,
                              void* d_out, int out_size)
{
    const float* obj   = (const float*)d_in[0];
    const float* pred  = (const float*)d_in[1];
    const int*   edges = (const int*)  d_in[2];
    const float* W1 = (const float*)d_in[3];
    const float* b1 = (const float*)d_in[4];
    const float* W2 = (const float*)d_in[5];
    const float* b2 = (const float*)d_in[6];
    const float* W3 = (const float*)d_in[7];
    const float* b3 = (const float*)d_in[8];
    const float* W4 = (const float*)d_in[9];
    const float* b4 = (const float*)d_in[10];

    float* out     = (float*)d_out;
    float* out_obj = out;                           // (NOBJ, 128)
    float* out_p   = out + (size_t)NOBJ * D_OUTK;   // (NT, 128)

    cudaFuncSetAttribute(hgemm<0>, cudaFuncAttributeMaxDynamicSharedMemorySize, SMEMB);
    cudaFuncSetAttribute(hgemm<1>, cudaFuncAttributeMaxDynamicSharedMemorySize, SMEMB);
    cudaFuncSetAttribute(hgemm<2>, cudaFuncAttributeMaxDynamicSharedMemorySize, SMEMB);
    cudaFuncSetAttribute(hgemm<3>, cudaFuncAttributeMaxDynamicSharedMemorySize, SMEMB);

    zero_counts<<<(NOBJ + 255) / 256, 256>>>();
    prep_kernel<<<NB_TOTAL, 256>>>(obj, pred, edges, W1, W2, W3, W4);

    int gy_t = (NT + BM - 1) / BM;    // 1563
    int gy_o = (NOBJ + BM - 1) / BM;  // 782

    hgemm<0><<<dim3(4, gy_t), 256, SMEMB>>>(edges, b1, nullptr, NT);
    hgemm<1><<<dim3(9, gy_t), 256, SMEMB>>>(edges, b2, out_p, NT);
    normalize_h<<<(NOBJ * HID / 4 + 255) / 256, 256>>>();
    hgemm<2><<<dim3(4, gy_o), 256, SMEMB>>>(edges, b3, nullptr, NOBJ);
    hgemm<3><<<dim3(1, gy_o), 256, SMEMB>>>(edges, b4, out_obj, NOBJ);
}

// round 12
// speedup vs baseline: 1.1986x; 1.0324x over previous
#include <cuda_runtime.h>
#include <cuda_fp16.h>
#include <cstdint>

#define D_IN   128
#define HID    512
#define D_OUTK 128
#define NOBJ   100000
#define NT     200000

#define BM 128
#define BN 128
#define BK 64                      // halfs per stage-chunk (128 B per row)
#define A_BYTES (BM * BK * 2)      // 16 KB
#define STAGE_BYTES (2 * A_BYTES)  // A + B = 32 KB
#define NSTAGE 3
#define SMEMB (NSTAGE * STAGE_BYTES)

// Scratch (device globals — no allocation allowed)
__device__ __align__(16) __half g_h[(size_t)NT * HID];
__device__ __align__(16) float  g_pooled[(size_t)NOBJ * HID];
__device__ __align__(16) __half g_pooledh[(size_t)NOBJ * HID];
__device__ __align__(16) __half g_tmph[(size_t)NOBJ * HID];
__device__ __align__(16) float  g_counts[NOBJ];
__device__ __align__(16) __half g_objth[(size_t)NOBJ * D_IN];
__device__ __align__(16) __half g_predth[(size_t)NT * D_IN];
// Weights transposed to [n][k], fp16
__device__ __align__(16) __half g_W1T[(size_t)HID * 384];
__device__ __align__(16) __half g_W2T[(size_t)1152 * HID];
__device__ __align__(16) __half g_W3T[(size_t)HID * HID];
__device__ __align__(16) __half g_W4T[(size_t)D_OUTK * HID];

// ---------------------------------------------------------------------------
__device__ __forceinline__ void mma_f16(float* c, const uint32_t* a, const uint32_t* b) {
    asm volatile(
        "mma.sync.aligned.m16n8k16.row.col.f32.f16.f16.f32 "
        "{%0,%1,%2,%3}, {%4,%5,%6,%7}, {%8,%9}, {%0,%1,%2,%3};"
        : "+f"(c[0]), "+f"(c[1]), "+f"(c[2]), "+f"(c[3])
        : "r"(a[0]), "r"(a[1]), "r"(a[2]), "r"(a[3]), "r"(b[0]), "r"(b[1]));
}

__device__ __forceinline__ void ldsm4(uint32_t& r0, uint32_t& r1, uint32_t& r2,
                                      uint32_t& r3, uint32_t addr) {
    asm volatile("ldmatrix.sync.aligned.m8n8.x4.shared.b16 {%0,%1,%2,%3}, [%4];"
                 : "=r"(r0), "=r"(r1), "=r"(r2), "=r"(r3) : "r"(addr));
}

__device__ __forceinline__ void cp16(uint32_t d, const void* s, int sz) {
    asm volatile("cp.async.cg.shared.global [%0], [%1], 16, %2;"
                 :: "r"(d), "l"(s), "r"(sz));
}
#define CP_COMMIT() asm volatile("cp.async.commit_group;" ::: "memory")
#define CP_WAIT1()  asm volatile("cp.async.wait_group 1;" ::: "memory")

__device__ __forceinline__ void red_add_v4(float* addr, float a, float b,
                                           float c, float d) {
    asm volatile("red.global.add.v4.f32 [%0], {%1, %2, %3, %4};"
                 :: "l"(addr), "f"(a), "f"(b), "f"(c), "f"(d) : "memory");
}

// ---------------------------------------------------------------------------
__global__ void zero_counts() {
    int i = blockIdx.x * blockDim.x + threadIdx.x;
    if (i < NOBJ) g_counts[i] = 0.f;
}

// Section-dispatched prep: pooled zero | cvt obj | cvt pred | cvtT W1-4 | count
#define NB_POOL  50000
#define NB_OBJ   12500
#define NB_PRED  25000
#define NB_W1    768
#define NB_W2    2304
#define NB_W3    1024
#define NB_W4    256
#define NB_CNT   782
#define NB_TOTAL (NB_POOL + NB_OBJ + NB_PRED + NB_W1 + NB_W2 + NB_W3 + NB_W4 + NB_CNT)

__device__ __forceinline__ void cvt_sec(const float* src, __half* dst, int i) {
    float4 v = ((const float4*)src)[i];
    __half2* d2 = (__half2*)dst;
    d2[2 * i]     = __floats2half2_rn(v.x, v.y);
    d2[2 * i + 1] = __floats2half2_rn(v.z, v.w);
}
__device__ __forceinline__ void cvtT_sec(const float* W, __half* WT, int K, int N, int idx) {
    int n = idx / K, k = idx - n * K;
    WT[idx] = __float2half_rn(W[(size_t)k * N + n]);
}

__global__ void prep_kernel(const float* __restrict__ obj, const float* __restrict__ pred,
                            const int* __restrict__ edges,
                            const float* __restrict__ W1, const float* __restrict__ W2,
                            const float* __restrict__ W3, const float* __restrict__ W4)
{
    int b = blockIdx.x;
    int t = threadIdx.x;
    if (b < NB_POOL) {
        int i = b * 256 + t;
        ((float4*)g_pooled)[i] = make_float4(0.f, 0.f, 0.f, 0.f);
        return;
    }
    b -= NB_POOL;
    if (b < NB_OBJ)  { cvt_sec(obj,  g_objth,  b * 256 + t); return; }
    b -= NB_OBJ;
    if (b < NB_PRED) { cvt_sec(pred, g_predth, b * 256 + t); return; }
    b -= NB_PRED;
    if (b < NB_W1) { cvtT_sec(W1, g_W1T, 384, 512,  b * 256 + t); return; }
    b -= NB_W1;
    if (b < NB_W2) { cvtT_sec(W2, g_W2T, 512, 1152, b * 256 + t); return; }
    b -= NB_W2;
    if (b < NB_W3) { cvtT_sec(W3, g_W3T, 512, 512,  b * 256 + t); return; }
    b -= NB_W3;
    if (b < NB_W4) { cvtT_sec(W4, g_W4T, 512, 128,  b * 256 + t); return; }
    b -= NB_W4;
    {
        int e = b * 256 + t;
        if (e < NT) {
            atomicAdd(&g_counts[edges[2 * e]],     1.f);
            atomicAdd(&g_counts[edges[2 * e + 1]], 1.f);
        }
    }
}

__global__ void normalize_h() {
    int i = blockIdx.x * blockDim.x + threadIdx.x;
    if (i < (NOBJ * HID) / 4) {
        int r = i >> 7;
        float sc = 1.f / fmaxf(g_counts[r], 1.f);
        float4 v = ((const float4*)g_pooled)[i];
        __half2* d2 = (__half2*)g_pooledh;
        d2[2 * i]     = __floats2half2_rn(v.x * sc, v.y * sc);
        d2[2 * i + 1] = __floats2half2_rn(v.z * sc, v.w * sc);
    }
}

// ---------------------------------------------------------------------------
// MF = m-fragments per warp (2 -> 32x64 tile, 256 thr; 4 -> 64x64 tile, 128 thr).
// Warp layout: (8/MF) m-warps x 2 n-warps. CTA tile 128x128 in all cases.
// KIND 0: g_h    = h(relu(gather @ W1T + b1))        M=NT,   K=384, N=512
// KIND 1: scatter/out_p from relu(g_h @ W2T + b2)    M=NT,   K=512, N=1152
// KIND 2: g_tmph = h(relu(pooledh @ W3T + b3))       M=NOBJ, K=512, N=512
// KIND 3: out_obj = relu(g_tmph @ W4T + b4)          M=NOBJ, K=512, N=128
template<int KIND, int MF>
__global__ void __launch_bounds__(512 / MF, 2) hgemm(const int* __restrict__ edges,
                                                     const float* __restrict__ bias,
                                                     float* __restrict__ out, int M)
{
    constexpr int K  = (KIND == 0) ? 384 : 512;
    constexpr int KT = K / BK;
    constexpr int MWARPS = 8 / MF;          // m-warps
    constexpr int NTH = MWARPS * 2 * 32;    // threads
    constexpr int LIT = 1024 / NTH;         // load iterations per operand

    extern __shared__ __align__(16) char sh[];
    uint32_t sm = (uint32_t)__cvta_generic_to_shared(sh);

    int tid = threadIdx.x, lane = tid & 31, w = tid >> 5;
    int wm = w % MWARPS, wn = w / MWARPS;
    int gr = lane >> 2, ct = lane & 3;
    int sel = lane >> 3, lr = lane & 7;          // ldmatrix lane roles
    int row0 = blockIdx.y * BM;
    int col0 = blockIdx.x * BN;

    int mode = 0, pcol = 0;                      // KIND 1 column routing
    if (KIND == 1) {
        int bx = blockIdx.x;
        if (bx < 4)       { mode = 0; pcol = bx * 128; }
        else if (bx == 4) { mode = 1; pcol = 0; }
        else              { mode = 2; pcol = (bx - 5) * 128; }
    }

    const __half* Wt   = (KIND == 0) ? g_W1T : (KIND == 1) ? g_W2T
                       : (KIND == 2) ? g_W3T : g_W4T;
    const __half* Amat = (KIND == 1) ? g_h : (KIND == 2) ? g_pooledh : g_tmph;

    float acc[MF][8][4];
#pragma unroll
    for (int i = 0; i < MF; i++)
#pragma unroll
        for (int j = 0; j < 8; j++)
#pragma unroll
            for (int k = 0; k < 4; k++) acc[i][j][k] = 0.f;

    auto load_stage = [&](int kt) {
        int k0 = kt * BK;                          // in halfs
        uint32_t ab = sm + (uint32_t)(kt % NSTAGE) * STAGE_BYTES;
        uint32_t bb = ab + A_BYTES;
#pragma unroll
        for (int i = 0; i < LIT; i++) {            // A: 128 rows x 8 chunks
            int f = tid + i * NTH;
            int m = f >> 3, ch = f & 7;
            int mg = row0 + m;
            int sz = (mg < M) ? 16 : 0;
            int mc = (mg < M) ? mg : M - 1;
            const char* src;
            if (KIND == 0) {
                int region = k0 >> 7;
                int bo = (k0 & 127) * 2;
                if (region == 0)      src = (const char*)(g_objth  + (size_t)edges[2 * mc]     * 128) + bo;
                else if (region == 1) src = (const char*)(g_predth + (size_t)mc                * 128) + bo;
                else                  src = (const char*)(g_objth  + (size_t)edges[2 * mc + 1] * 128) + bo;
            } else {
                src = (const char*)(Amat + (size_t)mc * K + k0);
            }
            cp16(ab + (uint32_t)(m * 128 + ((ch ^ (m & 7)) * 16)), src + ch * 16, sz);
        }
#pragma unroll
        for (int i = 0; i < LIT; i++) {            // B: 128 n-rows x 8 chunks
            int f = tid + i * NTH;
            int n = f >> 3, ch = f & 7;
            const char* src = (const char*)(Wt + (size_t)(col0 + n) * K + k0) + ch * 16;
            cp16(bb + (uint32_t)(n * 128 + ((ch ^ (n & 7)) * 16)), src, 16);
        }
    };

    int a_row[MF];
#pragma unroll
    for (int mf = 0; mf < MF; mf++)
        a_row[mf] = wm * (16 * MF) + mf * 16 + lr + ((sel & 1) << 3);
    int b_row[4];
#pragma unroll
    for (int p = 0; p < 4; p++)
        b_row[p] = wn * 64 + p * 16 + lr + ((sel >> 1) << 3);

    auto mma_stage = [&](int b) {
        uint32_t abase = sm + (uint32_t)b * STAGE_BYTES;
        uint32_t bbase = abase + A_BYTES;
#pragma unroll
        for (int kb = 0; kb < BK / 16; kb++) {
            uint32_t a[MF][4], bf[8][2];
            int a_ch = 2 * kb + (sel >> 1);
#pragma unroll
            for (int mf = 0; mf < MF; mf++) {
                int r = a_row[mf];
                uint32_t addr = abase + (uint32_t)(r * 128 + ((a_ch ^ (r & 7)) * 16));
                ldsm4(a[mf][0], a[mf][1], a[mf][2], a[mf][3], addr);
            }
            int b_ch = 2 * kb + (sel & 1);
#pragma unroll
            for (int p = 0; p < 4; p++) {
                int r = b_row[p];
                uint32_t addr = bbase + (uint32_t)(r * 128 + ((b_ch ^ (r & 7)) * 16));
                ldsm4(bf[2 * p][0], bf[2 * p][1], bf[2 * p + 1][0], bf[2 * p + 1][1], addr);
            }
#pragma unroll
            for (int mf = 0; mf < MF; mf++)
#pragma unroll
                for (int nf = 0; nf < 8; nf++)
                    mma_f16(acc[mf][nf], a[mf], bf[nf]);
        }
    };

    load_stage(0); CP_COMMIT();
    load_stage(1); CP_COMMIT();

    for (int kt = 0; kt < KT; kt++) {
        CP_WAIT1();
        __syncthreads();
        if (kt + 2 < KT) load_stage(kt + 2);
        CP_COMMIT();
        mma_stage(kt % NSTAGE);
    }

    // ---- epilogue ----
    float bb[8][2];
#pragma unroll
    for (int nf = 0; nf < 8; nf++) {
        int c = col0 + wn * 64 + nf * 8 + ct * 2;
        bb[nf][0] = bias[c]; bb[nf][1] = bias[c + 1];
    }

    if (KIND == 1 && mode != 1) {
        // Shuffle-paired v4 scatter: even ct lane reds row r, odd ct reds row r+8.
        int halfsel = ct & 1;
        int q = ct >> 1;
#pragma unroll
        for (int mf = 0; mf < MF; mf++) {
            int rbase = row0 + wm * (16 * MF) + mf * 16 + gr;
            int myrow = rbase + (halfsel ? 8 : 0);
            bool valid = myrow < M;
            int sidx = 0;
            if (valid) sidx = (mode == 0) ? edges[2 * myrow] : edges[2 * myrow + 1];
            float* dstrow = g_pooled + (size_t)sidx * HID + pcol + wn * 64 + q * 4;
#pragma unroll
            for (int nf = 0; nf < 8; nf++) {
                float v0 = fmaxf(acc[mf][nf][0] + bb[nf][0], 0.f);
                float v1 = fmaxf(acc[mf][nf][1] + bb[nf][1], 0.f);
                float v2 = fmaxf(acc[mf][nf][2] + bb[nf][0], 0.f);
                float v3 = fmaxf(acc[mf][nf][3] + bb[nf][1], 0.f);
                float s0 = halfsel ? v0 : v2;
                float s1 = halfsel ? v1 : v3;
                float p0 = __shfl_xor_sync(0xffffffffu, s0, 1);
                float p1 = __shfl_xor_sync(0xffffffffu, s1, 1);
                float o0 = halfsel ? p0 : v0;
                float o1 = halfsel ? p1 : v1;
                float o2 = halfsel ? v2 : p0;
                float o3 = halfsel ? v3 : p1;
                if (valid) red_add_v4(dstrow + nf * 8, o0, o1, o2, o3);
            }
        }
    } else {
#pragma unroll
        for (int mf = 0; mf < MF; mf++)
#pragma unroll
            for (int half = 0; half < 2; half++) {
                int r = row0 + wm * (16 * MF) + mf * 16 + gr + half * 8;
                if (r >= M) continue;
                int cbase = wn * 64 + ct * 2;
                if (KIND == 0 || KIND == 2) {
                    __half* dst = ((KIND == 0) ? g_h : g_tmph) + (size_t)r * HID + col0 + cbase;
#pragma unroll
                    for (int nf = 0; nf < 8; nf++) {
                        float x = fmaxf(acc[mf][nf][half * 2 + 0] + bb[nf][0], 0.f);
                        float y = fmaxf(acc[mf][nf][half * 2 + 1] + bb[nf][1], 0.f);
                        *(__half2*)(dst + nf * 8) = __floats2half2_rn(x, y);
                    }
                } else {  // KIND 3 or KIND 1 mode==1: contiguous float stores
                    float* dst = out + (size_t)r * D_OUTK + cbase;
#pragma unroll
                    for (int nf = 0; nf < 8; nf++) {
                        float2 o;
                        o.x = fmaxf(acc[mf][nf][half * 2 + 0] + bb[nf][0], 0.f);
                        o.y = fmaxf(acc[mf][nf][half * 2 + 1] + bb[nf][1], 0.f);
                        *(float2*)(dst + nf * 8) = o;
                    }
                }
            }
    }
}

// ---------------------------------------------------------------------------
extern "C" void kernel_launch(void* const* d_in, const int* in_sizes, int n_in,
                              void* d_out, int out_size)
{
    const float* obj   = (const float*)d_in[0];
    const float* pred  = (const float*)d_in[1];
    const int*   edges = (const int*)  d_in[2];
    const float* W1 = (const float*)d_in[3];
    const float* b1 = (const float*)d_in[4];
    const float* W2 = (const float*)d_in[5];
    const float* b2 = (const float*)d_in[6];
    const float* W3 = (const float*)d_in[7];
    const float* b3 = (const float*)d_in[8];
    const float* W4 = (const float*)d_in[9];
    const float* b4 = (const float*)d_in[10];

    float* out     = (float*)d_out;
    float* out_obj = out;                           // (NOBJ, 128)
    float* out_p   = out + (size_t)NOBJ * D_OUTK;   // (NT, 128)

    cudaFuncSetAttribute((const void*)hgemm<0, 2>, cudaFuncAttributeMaxDynamicSharedMemorySize, SMEMB);
    cudaFuncSetAttribute((const void*)hgemm<1, 4>, cudaFuncAttributeMaxDynamicSharedMemorySize, SMEMB);
    cudaFuncSetAttribute((const void*)hgemm<2, 4>, cudaFuncAttributeMaxDynamicSharedMemorySize, SMEMB);
    cudaFuncSetAttribute((const void*)hgemm<3, 2>, cudaFuncAttributeMaxDynamicSharedMemorySize, SMEMB);

    zero_counts<<<(NOBJ + 255) / 256, 256>>>();
    prep_kernel<<<NB_TOTAL, 256>>>(obj, pred, edges, W1, W2, W3, W4);

    int gy_t = (NT + BM - 1) / BM;    // 1563
    int gy_o = (NOBJ + BM - 1) / BM;  // 782

    hgemm<0, 2><<<dim3(4, gy_t), 256, SMEMB>>>(edges, b1, nullptr, NT);
    hgemm<1, 4><<<dim3(9, gy_t), 128, SMEMB>>>(edges, b2, out_p, NT);
    normalize_h<<<(NOBJ * HID / 4 + 255) / 256, 256>>>();
    hgemm<2, 4><<<dim3(4, gy_o), 128, SMEMB>>>(edges, b3, nullptr, NOBJ);
    hgemm<3, 2><<<dim3(1, gy_o), 256, SMEMB>>>(edges, b4, out_obj, NOBJ);
}

// round 13
// speedup vs baseline: 1.2586x; 1.0501x over previous
#include <cuda_runtime.h>
#include <cuda_fp16.h>
#include <cstdint>

#define D_IN   128
#define HID    512
#define D_OUTK 128
#define NOBJ   100000
#define NT     200000

#define BM 128
#define BN 128
#define BK 64
#define KTILE_H 8192                     // halfs per 16KB tile (128 rows x 64 halfs)
#define KTILE_B 16384
#define STAGE_BYTES (2 * KTILE_B)        // A + B = 32 KB
#define NSTAGE 3
#define SMEMB (1024 + NSTAGE * STAGE_BYTES)
#define NPANEL_T 1563                    // ceil(NT/128)
#define NPANEL_O 782                     // ceil(NOBJ/128)

// Scratch (device globals — no allocation allowed). Zero-init; tails beyond M
// are never written and stay zero across replays.
__device__ __align__(16) __half g_h[(size_t)NPANEL_T * 8 * KTILE_H];   // packed tiles
__device__ __align__(16) float  g_pooled[(size_t)NOBJ * HID];
__device__ __align__(16) __half g_ph[(size_t)NPANEL_O * 8 * KTILE_H];  // pooledh packed
__device__ __align__(16) __half g_tp[(size_t)NPANEL_O * 8 * KTILE_H];  // tmph packed
__device__ __align__(16) float  g_counts[NOBJ];
__device__ __align__(16) __half g_objth[(size_t)NOBJ * D_IN];
__device__ __align__(16) __half g_predth[(size_t)NT * D_IN];
// Weights packed as [nblock][ktile][16KB swizzled tile]
__device__ __align__(16) __half g_W1P[(size_t)4 * 6 * KTILE_H];
__device__ __align__(16) __half g_W2P[(size_t)9 * 8 * KTILE_H];
__device__ __align__(16) __half g_W3P[(size_t)4 * 8 * KTILE_H];
__device__ __align__(16) __half g_W4P[(size_t)1 * 8 * KTILE_H];

// ---------------------------------------------------------------------------
__device__ __forceinline__ void mma_f16(float* c, const uint32_t* a, const uint32_t* b) {
    asm volatile(
        "mma.sync.aligned.m16n8k16.row.col.f32.f16.f16.f32 "
        "{%0,%1,%2,%3}, {%4,%5,%6,%7}, {%8,%9}, {%0,%1,%2,%3};"
        : "+f"(c[0]), "+f"(c[1]), "+f"(c[2]), "+f"(c[3])
        : "r"(a[0]), "r"(a[1]), "r"(a[2]), "r"(a[3]), "r"(b[0]), "r"(b[1]));
}

__device__ __forceinline__ void ldsm4(uint32_t& r0, uint32_t& r1, uint32_t& r2,
                                      uint32_t& r3, uint32_t addr) {
    asm volatile("ldmatrix.sync.aligned.m8n8.x4.shared.b16 {%0,%1,%2,%3}, [%4];"
                 : "=r"(r0), "=r"(r1), "=r"(r2), "=r"(r3) : "r"(addr));
}

__device__ __forceinline__ void cp16(uint32_t d, const void* s, int sz) {
    asm volatile("cp.async.cg.shared.global [%0], [%1], 16, %2;"
                 :: "r"(d), "l"(s), "r"(sz));
}
#define CP_COMMIT() asm volatile("cp.async.commit_group;" ::: "memory")
#define CP_WAIT1()  asm volatile("cp.async.wait_group 1;" ::: "memory")

__device__ __forceinline__ void bulk_g2s(uint32_t dst, const void* src,
                                         int bytes, uint32_t mbar) {
    asm volatile("cp.async.bulk.shared::cta.global.mbarrier::complete_tx::bytes "
                 "[%0], [%1], %2, [%3];"
                 :: "r"(dst), "l"(src), "r"(bytes), "r"(mbar) : "memory");
}

#define MBARRIER_INIT(mbar, count) \
    asm volatile("mbarrier.init.shared.b64 [%0], %1;" \
                 :: "r"((uint32_t)(mbar)), "r"((uint32_t)(count)) : "memory")
#define MBARRIER_EXPECT_TX(mbar, tx) \
    asm volatile("mbarrier.arrive.expect_tx.shared.b64 _, [%0], %1;" \
                 :: "r"((uint32_t)(mbar)), "r"((uint32_t)(tx)) : "memory")
#define MBARRIER_WAIT_PARITY(mbar_smem_addr, phase_parity) do { \
    uint32_t _mbar = (uint32_t)(mbar_smem_addr); \
    uint32_t _parity = (uint32_t)(phase_parity); \
    uint32_t _done; \
    asm volatile("{\n\t.reg .pred p;\n\t" \
        "mbarrier.try_wait.parity.acquire.cta.shared::cta.b64 p, [%1], %2;\n\t" \
        "selp.b32 %0, 1, 0, p;\n\t}" \
        : "=r"(_done) : "r"(_mbar), "r"(_parity) : "memory"); \
    if (!_done) { \
        asm volatile("{\n\t.reg .pred P1;\n\t" \
            "WAIT_LOOP_%=:\n\t" \
            "mbarrier.try_wait.parity.acquire.cta.shared::cta.b64 P1, [%0], %1, 0x989680;\n\t" \
            "@P1 bra.uni WAIT_DONE_%=;\n\t" \
            "bra.uni WAIT_LOOP_%=;\n\t" \
            "WAIT_DONE_%=:\n\t}" \
            :: "r"(_mbar), "r"(_parity) : "memory"); \
    } \
} while(0)

__device__ __forceinline__ void red_add_v4(float* addr, float a, float b,
                                           float c, float d) {
    asm volatile("red.global.add.v4.f32 [%0], {%1, %2, %3, %4};"
                 :: "l"(addr), "f"(a), "f"(b), "f"(c), "f"(d) : "memory");
}

// Packed tile offset (in halfs) for element (row r, col c) of a K=512 matrix.
__device__ __forceinline__ size_t packed_off(int r, int c) {
    int p = r >> 7, m = r & 127, kt = c >> 6, ch = (c & 63) >> 3, rem = c & 7;
    return ((size_t)(p * 8 + kt)) * KTILE_H
         + (size_t)((m * 128 + ((ch ^ (m & 7)) * 16)) >> 1) + rem;
}

// ---------------------------------------------------------------------------
__global__ void zero_counts() {
    int i = blockIdx.x * blockDim.x + threadIdx.x;
    if (i < NOBJ) g_counts[i] = 0.f;
}

#define NB_POOL  50000
#define NB_OBJ   12500
#define NB_PRED  25000
#define NB_W1    768
#define NB_W2    2304
#define NB_W3    1024
#define NB_W4    256
#define NB_CNT   782
#define NB_TOTAL (NB_POOL + NB_OBJ + NB_PRED + NB_W1 + NB_W2 + NB_W3 + NB_W4 + NB_CNT)

__device__ __forceinline__ void cvt_sec(const float* src, __half* dst, int i) {
    float4 v = ((const float4*)src)[i];
    __half2* d2 = (__half2*)dst;
    d2[2 * i]     = __floats2half2_rn(v.x, v.y);
    d2[2 * i + 1] = __floats2half2_rn(v.z, v.w);
}
// Pack W (K x N, row-major) into swizzled tiles WP[nb][kt][16KB]
__device__ __forceinline__ void cvtT_pack(const float* W, __half* WP, int K, int N, int idx) {
    int n = idx / K, k = idx - n * K;
    int nb = n >> 7, nl = n & 127, kt = k >> 6, ch = (k & 63) >> 3, rem = k & 7;
    int KTI = K / 64;
    size_t off = ((size_t)(nb * KTI + kt)) * KTILE_H
               + (size_t)((nl * 128 + ((ch ^ (nl & 7)) * 16)) >> 1) + rem;
    WP[off] = __float2half_rn(W[(size_t)k * N + n]);
}

__global__ void prep_kernel(const float* __restrict__ obj, const float* __restrict__ pred,
                            const int* __restrict__ edges,
                            const float* __restrict__ W1, const float* __restrict__ W2,
                            const float* __restrict__ W3, const float* __restrict__ W4)
{
    int b = blockIdx.x;
    int t = threadIdx.x;
    if (b < NB_POOL) {
        int i = b * 256 + t;
        ((float4*)g_pooled)[i] = make_float4(0.f, 0.f, 0.f, 0.f);
        return;
    }
    b -= NB_POOL;
    if (b < NB_OBJ)  { cvt_sec(obj,  g_objth,  b * 256 + t); return; }
    b -= NB_OBJ;
    if (b < NB_PRED) { cvt_sec(pred, g_predth, b * 256 + t); return; }
    b -= NB_PRED;
    if (b < NB_W1) { cvtT_pack(W1, g_W1P, 384, 512,  b * 256 + t); return; }
    b -= NB_W1;
    if (b < NB_W2) { cvtT_pack(W2, g_W2P, 512, 1152, b * 256 + t); return; }
    b -= NB_W2;
    if (b < NB_W3) { cvtT_pack(W3, g_W3P, 512, 512,  b * 256 + t); return; }
    b -= NB_W3;
    if (b < NB_W4) { cvtT_pack(W4, g_W4P, 512, 128,  b * 256 + t); return; }
    b -= NB_W4;
    {
        int e = b * 256 + t;
        if (e < NT) {
            atomicAdd(&g_counts[edges[2 * e]],     1.f);
            atomicAdd(&g_counts[edges[2 * e + 1]], 1.f);
        }
    }
}

// g_ph[packed(r,c)] = half(pooled[r][c] / max(counts[r],1))
__global__ void normalize_h() {
    int i = blockIdx.x * blockDim.x + threadIdx.x;
    if (i < (NOBJ * HID) / 4) {
        int r = i >> 7;
        int c = (i & 127) * 4;
        float sc = 1.f / fmaxf(g_counts[r], 1.f);
        float4 v = ((const float4*)g_pooled)[i];
        __half* dst = g_ph + packed_off(r, c);
        *(__half2*)(dst)     = __floats2half2_rn(v.x * sc, v.y * sc);
        *(__half2*)(dst + 2) = __floats2half2_rn(v.z * sc, v.w * sc);
    }
}

// ---------------------------------------------------------------------------
// MF = m-fragments per warp (2 -> 32x64 tile, 256 thr; 4 -> 64x64 tile, 128 thr).
// KIND 0: g_h(packed) = h(relu(gather @ W1 + b1))     M=NT,   K=384  [cp.async path]
// KIND 1: scatter/out_p from relu(h @ W2 + b2)        M=NT,   K=512  [bulk path]
// KIND 2: g_tp(packed) = h(relu(ph @ W3 + b3))        M=NOBJ, K=512  [bulk path]
// KIND 3: out_obj = relu(tp @ W4 + b4)                M=NOBJ, K=512  [bulk path]
template<int KIND, int MF>
__global__ void __launch_bounds__(512 / MF, 2) hgemm(const int* __restrict__ edges,
                                                     const float* __restrict__ bias,
                                                     float* __restrict__ out, int M)
{
    constexpr int K  = (KIND == 0) ? 384 : 512;
    constexpr int KT = K / BK;
    constexpr int MWARPS = 8 / MF;
    constexpr int NTH = MWARPS * 2 * 32;
    constexpr int LIT = 1024 / NTH;

    extern __shared__ __align__(16) char sh[];
    uint32_t sm = (uint32_t)__cvta_generic_to_shared(sh);
    uint32_t tiles = sm + 1024;

    int tid = threadIdx.x, lane = tid & 31, w = tid >> 5;
    int wm = w % MWARPS, wn = w / MWARPS;
    int gr = lane >> 2, ct = lane & 3;
    int sel = lane >> 3, lr = lane & 7;
    int row0 = blockIdx.y * BM;
    int col0 = blockIdx.x * BN;

    int mode = 0, pcol = 0;
    if (KIND == 1) {
        int bx = blockIdx.x;
        if (bx < 4)       { mode = 0; pcol = bx * 128; }
        else if (bx == 4) { mode = 1; pcol = 0; }
        else              { mode = 2; pcol = (bx - 5) * 128; }
    }

    // Packed sources
    const __half* Bsrc = (KIND == 0) ? g_W1P + (size_t)(blockIdx.x * 6) * KTILE_H
                       : (KIND == 1) ? g_W2P + (size_t)(blockIdx.x * 8) * KTILE_H
                       : (KIND == 2) ? g_W3P + (size_t)(blockIdx.x * 8) * KTILE_H
                                     : g_W4P;
    const __half* Asrc = (KIND == 1) ? g_h  + (size_t)(blockIdx.y * 8) * KTILE_H
                       : (KIND == 2) ? g_ph + (size_t)(blockIdx.y * 8) * KTILE_H
                                     : g_tp + (size_t)(blockIdx.y * 8) * KTILE_H;

    float acc[MF][8][4];
#pragma unroll
    for (int i = 0; i < MF; i++)
#pragma unroll
        for (int j = 0; j < 8; j++)
#pragma unroll
            for (int k = 0; k < 4; k++) acc[i][j][k] = 0.f;

    int a_row[MF];
#pragma unroll
    for (int mf = 0; mf < MF; mf++)
        a_row[mf] = wm * (16 * MF) + mf * 16 + lr + ((sel & 1) << 3);
    int b_row[4];
#pragma unroll
    for (int p = 0; p < 4; p++)
        b_row[p] = wn * 64 + p * 16 + lr + ((sel >> 1) << 3);

    auto mma_stage = [&](int b) {
        uint32_t abase = tiles + (uint32_t)b * STAGE_BYTES;
        uint32_t bbase = abase + KTILE_B;
#pragma unroll
        for (int kb = 0; kb < BK / 16; kb++) {
            uint32_t a[MF][4], bf[8][2];
            int a_ch = 2 * kb + (sel >> 1);
#pragma unroll
            for (int mf = 0; mf < MF; mf++) {
                int r = a_row[mf];
                ldsm4(a[mf][0], a[mf][1], a[mf][2], a[mf][3],
                      abase + (uint32_t)(r * 128 + ((a_ch ^ (r & 7)) * 16)));
            }
            int b_ch = 2 * kb + (sel & 1);
#pragma unroll
            for (int p = 0; p < 4; p++) {
                int r = b_row[p];
                ldsm4(bf[2 * p][0], bf[2 * p][1], bf[2 * p + 1][0], bf[2 * p + 1][1],
                      bbase + (uint32_t)(r * 128 + ((b_ch ^ (r & 7)) * 16)));
            }
#pragma unroll
            for (int mf = 0; mf < MF; mf++)
#pragma unroll
                for (int nf = 0; nf < 8; nf++)
                    mma_f16(acc[mf][nf], a[mf], bf[nf]);
        }
    };

    if (KIND == 0) {
        // ---- cp.async path (gather A + contiguous packed B) ----
        auto load_stage = [&](int kt) {
            int k0 = kt * BK;
            uint32_t ab = tiles + (uint32_t)(kt % NSTAGE) * STAGE_BYTES;
            uint32_t bb = ab + KTILE_B;
#pragma unroll
            for (int i = 0; i < LIT; i++) {
                int f = tid + i * NTH;
                int m = f >> 3, ch = f & 7;
                int mg = row0 + m;
                int sz = (mg < M) ? 16 : 0;
                int mc = (mg < M) ? mg : M - 1;
                int region = k0 >> 7;
                int bo = (k0 & 127) * 2;
                const char* src;
                if (region == 0)      src = (const char*)(g_objth  + (size_t)edges[2 * mc]     * 128) + bo;
                else if (region == 1) src = (const char*)(g_predth + (size_t)mc                * 128) + bo;
                else                  src = (const char*)(g_objth  + (size_t)edges[2 * mc + 1] * 128) + bo;
                cp16(ab + (uint32_t)(m * 128 + ((ch ^ (m & 7)) * 16)), src + ch * 16, sz);
            }
            const char* bs = (const char*)(Bsrc + (size_t)kt * KTILE_H);
#pragma unroll
            for (int i = 0; i < LIT; i++) {
                int f = tid + i * NTH;
                cp16(bb + (uint32_t)(f * 16), bs + f * 16, 16);
            }
        };
        load_stage(0); CP_COMMIT();
        load_stage(1); CP_COMMIT();
        for (int kt = 0; kt < KT; kt++) {
            CP_WAIT1();
            __syncthreads();
            if (kt + 2 < KT) load_stage(kt + 2);
            CP_COMMIT();
            mma_stage(kt % NSTAGE);
        }
    } else {
        // ---- bulk path ----
        if (tid == 0) {
            MBARRIER_INIT(sm, 1);
            MBARRIER_INIT(sm + 8, 1);
            MBARRIER_INIT(sm + 16, 1);
        }
        __syncthreads();
        auto issue = [&](int kt) {
            int b = kt % NSTAGE;
            uint32_t st = tiles + (uint32_t)b * STAGE_BYTES;
            MBARRIER_EXPECT_TX(sm + b * 8, STAGE_BYTES);
            bulk_g2s(st, Asrc + (size_t)kt * KTILE_H, KTILE_B, sm + b * 8);
            bulk_g2s(st + KTILE_B, Bsrc + (size_t)kt * KTILE_H, KTILE_B, sm + b * 8);
        };
        if (tid == 0) { issue(0); issue(1); }
        int ph0 = 0, ph1 = 0, ph2 = 0;
        for (int kt = 0; kt < KT; kt++) {
            int b = kt % NSTAGE;
            int& ph = (b == 0) ? ph0 : (b == 1) ? ph1 : ph2;
            MBARRIER_WAIT_PARITY(sm + b * 8, ph);
            ph ^= 1;
            __syncthreads();
            if (tid == 0 && kt + 2 < KT) issue(kt + 2);
            mma_stage(b);
        }
    }

    // ---- epilogue ----
    float bb[8][2];
#pragma unroll
    for (int nf = 0; nf < 8; nf++) {
        int c = col0 + wn * 64 + nf * 8 + ct * 2;
        bb[nf][0] = bias[c]; bb[nf][1] = bias[c + 1];
    }

    if (KIND == 1 && mode != 1) {
        int halfsel = ct & 1;
        int q = ct >> 1;
#pragma unroll
        for (int mf = 0; mf < MF; mf++) {
            int rbase = row0 + wm * (16 * MF) + mf * 16 + gr;
            int myrow = rbase + (halfsel ? 8 : 0);
            bool valid = myrow < M;
            int sidx = 0;
            if (valid) sidx = (mode == 0) ? edges[2 * myrow] : edges[2 * myrow + 1];
            float* dstrow = g_pooled + (size_t)sidx * HID + pcol + wn * 64 + q * 4;
#pragma unroll
            for (int nf = 0; nf < 8; nf++) {
                float v0 = fmaxf(acc[mf][nf][0] + bb[nf][0], 0.f);
                float v1 = fmaxf(acc[mf][nf][1] + bb[nf][1], 0.f);
                float v2 = fmaxf(acc[mf][nf][2] + bb[nf][0], 0.f);
                float v3 = fmaxf(acc[mf][nf][3] + bb[nf][1], 0.f);
                float s0 = halfsel ? v0 : v2;
                float s1 = halfsel ? v1 : v3;
                float p0 = __shfl_xor_sync(0xffffffffu, s0, 1);
                float p1 = __shfl_xor_sync(0xffffffffu, s1, 1);
                float o0 = halfsel ? p0 : v0;
                float o1 = halfsel ? p1 : v1;
                float o2 = halfsel ? v2 : p0;
                float o3 = halfsel ? v3 : p1;
                if (valid) red_add_v4(dstrow + nf * 8, o0, o1, o2, o3);
            }
        }
    } else {
#pragma unroll
        for (int mf = 0; mf < MF; mf++)
#pragma unroll
            for (int half = 0; half < 2; half++) {
                int r = row0 + wm * (16 * MF) + mf * 16 + gr + half * 8;
                if (r >= M) continue;
                if (KIND == 0 || KIND == 2) {
                    __half* base = (KIND == 0) ? g_h : g_tp;
#pragma unroll
                    for (int nf = 0; nf < 8; nf++) {
                        int c = col0 + wn * 64 + nf * 8 + ct * 2;
                        float x = fmaxf(acc[mf][nf][half * 2 + 0] + bb[nf][0], 0.f);
                        float y = fmaxf(acc[mf][nf][half * 2 + 1] + bb[nf][1], 0.f);
                        *(__half2*)(base + packed_off(r, c)) = __floats2half2_rn(x, y);
                    }
                } else {  // KIND 3 or KIND 1 mode==1
                    int cbase = wn * 64 + ct * 2;
                    float* dst = out + (size_t)r * D_OUTK + cbase;
#pragma unroll
                    for (int nf = 0; nf < 8; nf++) {
                        float2 o;
                        o.x = fmaxf(acc[mf][nf][half * 2 + 0] + bb[nf][0], 0.f);
                        o.y = fmaxf(acc[mf][nf][half * 2 + 1] + bb[nf][1], 0.f);
                        *(float2*)(dst + nf * 8) = o;
                    }
                }
            }
    }
}

// ---------------------------------------------------------------------------
extern "C" void kernel_launch(void* const* d_in, const int* in_sizes, int n_in,
                              void* d_out, int out_size)
{
    const float* obj   = (const float*)d_in[0];
    const float* pred  = (const float*)d_in[1];
    const int*   edges = (const int*)  d_in[2];
    const float* W1 = (const float*)d_in[3];
    const float* b1 = (const float*)d_in[4];
    const float* W2 = (const float*)d_in[5];
    const float* b2 = (const float*)d_in[6];
    const float* W3 = (const float*)d_in[7];
    const float* b3 = (const float*)d_in[8];
    const float* W4 = (const float*)d_in[9];
    const float* b4 = (const float*)d_in[10];

    float* out     = (float*)d_out;
    float* out_obj = out;                           // (NOBJ, 128)
    float* out_p   = out + (size_t)NOBJ * D_OUTK;   // (NT, 128)

    cudaFuncSetAttribute((const void*)hgemm<0, 2>, cudaFuncAttributeMaxDynamicSharedMemorySize, SMEMB);
    cudaFuncSetAttribute((const void*)hgemm<1, 4>, cudaFuncAttributeMaxDynamicSharedMemorySize, SMEMB);
    cudaFuncSetAttribute((const void*)hgemm<2, 4>, cudaFuncAttributeMaxDynamicSharedMemorySize, SMEMB);
    cudaFuncSetAttribute((const void*)hgemm<3, 2>, cudaFuncAttributeMaxDynamicSharedMemorySize, SMEMB);

    zero_counts<<<(NOBJ + 255) / 256, 256>>>();
    prep_kernel<<<NB_TOTAL, 256>>>(obj, pred, edges, W1, W2, W3, W4);

    int gy_t = (NT + BM - 1) / BM;    // 1563
    int gy_o = (NOBJ + BM - 1) / BM;  // 782

    hgemm<0, 2><<<dim3(4, gy_t), 256, SMEMB>>>(edges, b1, nullptr, NT);
    hgemm<1, 4><<<dim3(9, gy_t), 128, SMEMB>>>(edges, b2, out_p, NT);
    normalize_h<<<(NOBJ * HID / 4 + 255) / 256, 256>>>();
    hgemm<2, 4><<<dim3(4, gy_o), 128, SMEMB>>>(edges, b3, nullptr, NOBJ);
    hgemm<3, 2><<<dim3(1, gy_o), 256, SMEMB>>>(edges, b4, out_obj, NOBJ);
}

// round 14
// speedup vs baseline: 1.3077x; 1.0390x over previous
#include <cuda_runtime.h>
#include <cuda_fp16.h>
#include <cstdint>

#define D_IN   128
#define HID    512
#define D_OUTK 128
#define NOBJ   100000
#define NT     200000

#define BM 128
#define BN 128
#define BK 64
#define KTILE_H 8192                     // halfs per 16KB tile (128 rows x 64 halfs)
#define KTILE_B 16384
#define STAGE_BYTES (2 * KTILE_B)        // A + B = 32 KB
#define NSTAGE 3
#define SMEMB (1024 + NSTAGE * STAGE_BYTES)
#define NPANEL_T 1563                    // ceil(NT/128)
#define NPANEL_O 782                     // ceil(NOBJ/128)

// Scratch (device globals — no allocation allowed). Zero-init; tails beyond M
// are never written and stay zero across replays.
__device__ __align__(16) __half g_h[(size_t)NPANEL_T * 8 * KTILE_H];   // packed tiles
__device__ __align__(16) float  g_pooled[(size_t)NOBJ * HID];
__device__ __align__(16) __half g_ph[(size_t)NPANEL_O * 8 * KTILE_H];  // pooledh packed
__device__ __align__(16) __half g_tp[(size_t)NPANEL_O * 8 * KTILE_H];  // tmph packed
__device__ __align__(16) float  g_counts[NOBJ];
__device__ __align__(16) __half g_objth[(size_t)NOBJ * D_IN];
__device__ __align__(16) __half g_predth[(size_t)NT * D_IN];
// Weights packed as [nblock][ktile][16KB swizzled tile]
__device__ __align__(16) __half g_W1P[(size_t)4 * 6 * KTILE_H];
__device__ __align__(16) __half g_W2P[(size_t)9 * 8 * KTILE_H];
__device__ __align__(16) __half g_W3P[(size_t)4 * 8 * KTILE_H];
__device__ __align__(16) __half g_W4P[(size_t)1 * 8 * KTILE_H];

// ---------------------------------------------------------------------------
__device__ __forceinline__ void mma_f16(float* c, const uint32_t* a, const uint32_t* b) {
    asm volatile(
        "mma.sync.aligned.m16n8k16.row.col.f32.f16.f16.f32 "
        "{%0,%1,%2,%3}, {%4,%5,%6,%7}, {%8,%9}, {%0,%1,%2,%3};"
        : "+f"(c[0]), "+f"(c[1]), "+f"(c[2]), "+f"(c[3])
        : "r"(a[0]), "r"(a[1]), "r"(a[2]), "r"(a[3]), "r"(b[0]), "r"(b[1]));
}

__device__ __forceinline__ void ldsm4(uint32_t& r0, uint32_t& r1, uint32_t& r2,
                                      uint32_t& r3, uint32_t addr) {
    asm volatile("ldmatrix.sync.aligned.m8n8.x4.shared.b16 {%0,%1,%2,%3}, [%4];"
                 : "=r"(r0), "=r"(r1), "=r"(r2), "=r"(r3) : "r"(addr));
}

__device__ __forceinline__ void cp16(uint32_t d, const void* s, int sz) {
    asm volatile("cp.async.cg.shared.global [%0], [%1], 16, %2;"
                 :: "r"(d), "l"(s), "r"(sz));
}
#define CP_COMMIT() asm volatile("cp.async.commit_group;" ::: "memory")
#define CP_WAIT1()  asm volatile("cp.async.wait_group 1;" ::: "memory")

__device__ __forceinline__ void bulk_g2s(uint32_t dst, const void* src,
                                         int bytes, uint32_t mbar) {
    asm volatile("cp.async.bulk.shared::cta.global.mbarrier::complete_tx::bytes "
                 "[%0], [%1], %2, [%3];"
                 :: "r"(dst), "l"(src), "r"(bytes), "r"(mbar) : "memory");
}

#define MBARRIER_INIT(mbar, count) \
    asm volatile("mbarrier.init.shared.b64 [%0], %1;" \
                 :: "r"((uint32_t)(mbar)), "r"((uint32_t)(count)) : "memory")
#define MBARRIER_EXPECT_TX(mbar, tx) \
    asm volatile("mbarrier.arrive.expect_tx.shared.b64 _, [%0], %1;" \
                 :: "r"((uint32_t)(mbar)), "r"((uint32_t)(tx)) : "memory")
#define MBARRIER_ARRIVE(mbar) \
    asm volatile("mbarrier.arrive.shared.b64 _, [%0];" \
                 :: "r"((uint32_t)(mbar)) : "memory")
#define MBARRIER_WAIT_PARITY(mbar_smem_addr, phase_parity) do { \
    uint32_t _mbar = (uint32_t)(mbar_smem_addr); \
    uint32_t _parity = (uint32_t)(phase_parity); \
    uint32_t _done; \
    asm volatile("{\n\t.reg .pred p;\n\t" \
        "mbarrier.try_wait.parity.acquire.cta.shared::cta.b64 p, [%1], %2;\n\t" \
        "selp.b32 %0, 1, 0, p;\n\t}" \
        : "=r"(_done) : "r"(_mbar), "r"(_parity) : "memory"); \
    if (!_done) { \
        asm volatile("{\n\t.reg .pred P1;\n\t" \
            "WAIT_LOOP_%=:\n\t" \
            "mbarrier.try_wait.parity.acquire.cta.shared::cta.b64 P1, [%0], %1, 0x989680;\n\t" \
            "@P1 bra.uni WAIT_DONE_%=;\n\t" \
            "bra.uni WAIT_LOOP_%=;\n\t" \
            "WAIT_DONE_%=:\n\t}" \
            :: "r"(_mbar), "r"(_parity) : "memory"); \
    } \
} while(0)

__device__ __forceinline__ void red_add_v4(float* addr, float a, float b,
                                           float c, float d) {
    asm volatile("red.global.add.v4.f32 [%0], {%1, %2, %3, %4};"
                 :: "l"(addr), "f"(a), "f"(b), "f"(c), "f"(d) : "memory");
}

// Packed tile offset (in halfs) for element (row r, col c) of a K=512 matrix.
__device__ __forceinline__ size_t packed_off(int r, int c) {
    int p = r >> 7, m = r & 127, kt = c >> 6, ch = (c & 63) >> 3, rem = c & 7;
    return ((size_t)(p * 8 + kt)) * KTILE_H
         + (size_t)((m * 128 + ((ch ^ (m & 7)) * 16)) >> 1) + rem;
}

// ---------------------------------------------------------------------------
__global__ void zero_counts() {
    int i = blockIdx.x * blockDim.x + threadIdx.x;
    if (i < NOBJ) g_counts[i] = 0.f;
}

#define NB_POOL  50000
#define NB_OBJ   12500
#define NB_PRED  25000
#define NB_W1    768
#define NB_W2    2304
#define NB_W3    1024
#define NB_W4    256
#define NB_CNT   782
#define NB_TOTAL (NB_POOL + NB_OBJ + NB_PRED + NB_W1 + NB_W2 + NB_W3 + NB_W4 + NB_CNT)

__device__ __forceinline__ void cvt_sec(const float* src, __half* dst, int i) {
    float4 v = ((const float4*)src)[i];
    __half2* d2 = (__half2*)dst;
    d2[2 * i]     = __floats2half2_rn(v.x, v.y);
    d2[2 * i + 1] = __floats2half2_rn(v.z, v.w);
}
// Pack W (K x N, row-major) into swizzled tiles WP[nb][kt][16KB]
__device__ __forceinline__ void cvtT_pack(const float* W, __half* WP, int K, int N, int idx) {
    int n = idx / K, k = idx - n * K;
    int nb = n >> 7, nl = n & 127, kt = k >> 6, ch = (k & 63) >> 3, rem = k & 7;
    int KTI = K / 64;
    size_t off = ((size_t)(nb * KTI + kt)) * KTILE_H
               + (size_t)((nl * 128 + ((ch ^ (nl & 7)) * 16)) >> 1) + rem;
    WP[off] = __float2half_rn(W[(size_t)k * N + n]);
}

__global__ void prep_kernel(const float* __restrict__ obj, const float* __restrict__ pred,
                            const int* __restrict__ edges,
                            const float* __restrict__ W1, const float* __restrict__ W2,
                            const float* __restrict__ W3, const float* __restrict__ W4)
{
    int b = blockIdx.x;
    int t = threadIdx.x;
    if (b < NB_POOL) {
        int i = b * 256 + t;
        ((float4*)g_pooled)[i] = make_float4(0.f, 0.f, 0.f, 0.f);
        return;
    }
    b -= NB_POOL;
    if (b < NB_OBJ)  { cvt_sec(obj,  g_objth,  b * 256 + t); return; }
    b -= NB_OBJ;
    if (b < NB_PRED) { cvt_sec(pred, g_predth, b * 256 + t); return; }
    b -= NB_PRED;
    if (b < NB_W1) { cvtT_pack(W1, g_W1P, 384, 512,  b * 256 + t); return; }
    b -= NB_W1;
    if (b < NB_W2) { cvtT_pack(W2, g_W2P, 512, 1152, b * 256 + t); return; }
    b -= NB_W2;
    if (b < NB_W3) { cvtT_pack(W3, g_W3P, 512, 512,  b * 256 + t); return; }
    b -= NB_W3;
    if (b < NB_W4) { cvtT_pack(W4, g_W4P, 512, 128,  b * 256 + t); return; }
    b -= NB_W4;
    {
        int e = b * 256 + t;
        if (e < NT) {
            atomicAdd(&g_counts[edges[2 * e]],     1.f);
            atomicAdd(&g_counts[edges[2 * e + 1]], 1.f);
        }
    }
}

// g_ph[packed(r,c)] = half(pooled[r][c] / max(counts[r],1))
__global__ void normalize_h() {
    int i = blockIdx.x * blockDim.x + threadIdx.x;
    if (i < (NOBJ * HID) / 4) {
        int r = i >> 7;
        int c = (i & 127) * 4;
        float sc = 1.f / fmaxf(g_counts[r], 1.f);
        float4 v = ((const float4*)g_pooled)[i];
        __half* dst = g_ph + packed_off(r, c);
        *(__half2*)(dst)     = __floats2half2_rn(v.x * sc, v.y * sc);
        *(__half2*)(dst + 2) = __floats2half2_rn(v.z * sc, v.w * sc);
    }
}

// ---------------------------------------------------------------------------
// MF = m-fragments per warp (2 -> 32x64 tile, 256 thr; 4 -> 64x64 tile, 128 thr).
// KIND 0: g_h(packed) = h(relu(gather @ W1 + b1))     M=NT,   K=384  [cp.async path]
// KIND 1: scatter/out_p from relu(h @ W2 + b2)        M=NT,   K=512  [bulk path]
// KIND 2: g_tp(packed) = h(relu(ph @ W3 + b3))        M=NOBJ, K=512  [bulk path]
// KIND 3: out_obj = relu(tp @ W4 + b4)                M=NOBJ, K=512  [bulk path]
template<int KIND, int MF>
__global__ void __launch_bounds__(512 / MF, 2) hgemm(const int* __restrict__ edges,
                                                     const float* __restrict__ bias,
                                                     float* __restrict__ out, int M)
{
    constexpr int K  = (KIND == 0) ? 384 : 512;
    constexpr int KT = K / BK;
    constexpr int MWARPS = 8 / MF;
    constexpr int NTH = MWARPS * 2 * 32;
    constexpr int NWARPS = NTH / 32;
    constexpr int LIT = 1024 / NTH;

    extern __shared__ __align__(16) char sh[];
    uint32_t sm = (uint32_t)__cvta_generic_to_shared(sh);
    uint32_t tiles = sm + 1024;
    // mbarriers: full[b] at sm + b*8, empty[b] at sm + 64 + b*8

    int tid = threadIdx.x, lane = tid & 31, w = tid >> 5;
    int wm = w % MWARPS, wn = w / MWARPS;
    int gr = lane >> 2, ct = lane & 3;
    int sel = lane >> 3, lr = lane & 7;
    int row0 = blockIdx.y * BM;
    int col0 = blockIdx.x * BN;

    int mode = 0, pcol = 0;
    if (KIND == 1) {
        int bx = blockIdx.x;
        if (bx < 4)       { mode = 0; pcol = bx * 128; }
        else if (bx == 4) { mode = 1; pcol = 0; }
        else              { mode = 2; pcol = (bx - 5) * 128; }
    }

    // Packed sources
    const __half* Bsrc = (KIND == 0) ? g_W1P + (size_t)(blockIdx.x * 6) * KTILE_H
                       : (KIND == 1) ? g_W2P + (size_t)(blockIdx.x * 8) * KTILE_H
                       : (KIND == 2) ? g_W3P + (size_t)(blockIdx.x * 8) * KTILE_H
                                     : g_W4P;
    const __half* Asrc = (KIND == 1) ? g_h  + (size_t)(blockIdx.y * 8) * KTILE_H
                       : (KIND == 2) ? g_ph + (size_t)(blockIdx.y * 8) * KTILE_H
                                     : g_tp + (size_t)(blockIdx.y * 8) * KTILE_H;

    float acc[MF][8][4];
#pragma unroll
    for (int i = 0; i < MF; i++)
#pragma unroll
        for (int j = 0; j < 8; j++)
#pragma unroll
            for (int k = 0; k < 4; k++) acc[i][j][k] = 0.f;

    int a_row[MF];
#pragma unroll
    for (int mf = 0; mf < MF; mf++)
        a_row[mf] = wm * (16 * MF) + mf * 16 + lr + ((sel & 1) << 3);
    int b_row[4];
#pragma unroll
    for (int p = 0; p < 4; p++)
        b_row[p] = wn * 64 + p * 16 + lr + ((sel >> 1) << 3);

    auto mma_stage = [&](int b) {
        uint32_t abase = tiles + (uint32_t)b * STAGE_BYTES;
        uint32_t bbase = abase + KTILE_B;
#pragma unroll
        for (int kb = 0; kb < BK / 16; kb++) {
            uint32_t a[MF][4], bf[8][2];
            int a_ch = 2 * kb + (sel >> 1);
#pragma unroll
            for (int mf = 0; mf < MF; mf++) {
                int r = a_row[mf];
                ldsm4(a[mf][0], a[mf][1], a[mf][2], a[mf][3],
                      abase + (uint32_t)(r * 128 + ((a_ch ^ (r & 7)) * 16)));
            }
            int b_ch = 2 * kb + (sel & 1);
#pragma unroll
            for (int p = 0; p < 4; p++) {
                int r = b_row[p];
                ldsm4(bf[2 * p][0], bf[2 * p][1], bf[2 * p + 1][0], bf[2 * p + 1][1],
                      bbase + (uint32_t)(r * 128 + ((b_ch ^ (r & 7)) * 16)));
            }
#pragma unroll
            for (int mf = 0; mf < MF; mf++)
#pragma unroll
                for (int nf = 0; nf < 8; nf++)
                    mma_f16(acc[mf][nf], a[mf], bf[nf]);
        }
    };

    if (KIND == 0) {
        // ---- cp.async path (gather A + contiguous packed B) ----
        auto load_stage = [&](int kt) {
            int k0 = kt * BK;
            uint32_t ab = tiles + (uint32_t)(kt % NSTAGE) * STAGE_BYTES;
            uint32_t bb = ab + KTILE_B;
#pragma unroll
            for (int i = 0; i < LIT; i++) {
                int f = tid + i * NTH;
                int m = f >> 3, ch = f & 7;
                int mg = row0 + m;
                int sz = (mg < M) ? 16 : 0;
                int mc = (mg < M) ? mg : M - 1;
                int region = k0 >> 7;
                int bo = (k0 & 127) * 2;
                const char* src;
                if (region == 0)      src = (const char*)(g_objth  + (size_t)edges[2 * mc]     * 128) + bo;
                else if (region == 1) src = (const char*)(g_predth + (size_t)mc                * 128) + bo;
                else                  src = (const char*)(g_objth  + (size_t)edges[2 * mc + 1] * 128) + bo;
                cp16(ab + (uint32_t)(m * 128 + ((ch ^ (m & 7)) * 16)), src + ch * 16, sz);
            }
            const char* bs = (const char*)(Bsrc + (size_t)kt * KTILE_H);
#pragma unroll
            for (int i = 0; i < LIT; i++) {
                int f = tid + i * NTH;
                cp16(bb + (uint32_t)(f * 16), bs + f * 16, 16);
            }
        };
        load_stage(0); CP_COMMIT();
        load_stage(1); CP_COMMIT();
        for (int kt = 0; kt < KT; kt++) {
            CP_WAIT1();
            __syncthreads();
            if (kt + 2 < KT) load_stage(kt + 2);
            CP_COMMIT();
            mma_stage(kt % NSTAGE);
        }
    } else {
        // ---- bulk path, sync-free producer/consumer mbarrier ring ----
        if (tid == 0) {
#pragma unroll
            for (int b = 0; b < NSTAGE; b++) {
                MBARRIER_INIT(sm + b * 8, 1);            // full: tx-based
                MBARRIER_INIT(sm + 64 + b * 8, NWARPS);  // empty: one arrive per warp
            }
        }
        __syncthreads();
        auto issue = [&](int kt) {
            int b = kt % NSTAGE;
            uint32_t st = tiles + (uint32_t)b * STAGE_BYTES;
            MBARRIER_EXPECT_TX(sm + b * 8, STAGE_BYTES);
            bulk_g2s(st, Asrc + (size_t)kt * KTILE_H, KTILE_B, sm + b * 8);
            bulk_g2s(st + KTILE_B, Bsrc + (size_t)kt * KTILE_H, KTILE_B, sm + b * 8);
        };
        bool lead = (tid == 0);
        if (lead) { issue(0); issue(1); if (2 < KT) issue(2); }
        int fph0 = 0, fph1 = 0, fph2 = 0;
        int eph0 = 0, eph1 = 0, eph2 = 0;
        for (int kt = 0; kt < KT; kt++) {
            int b = kt % NSTAGE;
            int& fph = (b == 0) ? fph0 : (b == 1) ? fph1 : fph2;
            MBARRIER_WAIT_PARITY(sm + b * 8, fph);
            fph ^= 1;
            if (lead && kt + NSTAGE < KT) {
                int b2 = (kt + NSTAGE) % NSTAGE;   // == b
                int& eph = (b2 == 0) ? eph0 : (b2 == 1) ? eph1 : eph2;
                // wait until all warps have consumed the PREVIOUS occupancy of b2
                // (arrivals from iteration kt - NSTAGE ... none for first issues)
                // Here: buffer b was just made full for kt; issuing kt+NSTAGE into b
                // requires consumption of kt (this iteration) -> must wait AFTER mma.
                // So defer the issue to after mma_stage + arrive (below).
            }
            mma_stage(b);
            if (lane == 0) MBARRIER_ARRIVE(sm + 64 + b * 8);
            if (lead && kt + NSTAGE < KT) {
                int& eph = (b == 0) ? eph0 : (b == 1) ? eph1 : eph2;
                MBARRIER_WAIT_PARITY(sm + 64 + b * 8, eph);
                eph ^= 1;
                issue(kt + NSTAGE);
            }
        }
    }

    // ---- epilogue ----
    float bb[8][2];
#pragma unroll
    for (int nf = 0; nf < 8; nf++) {
        int c = col0 + wn * 64 + nf * 8 + ct * 2;
        bb[nf][0] = bias[c]; bb[nf][1] = bias[c + 1];
    }

    if (KIND == 1 && mode != 1) {
        int halfsel = ct & 1;
        int q = ct >> 1;
#pragma unroll
        for (int mf = 0; mf < MF; mf++) {
            int rbase = row0 + wm * (16 * MF) + mf * 16 + gr;
            int myrow = rbase + (halfsel ? 8 : 0);
            bool valid = myrow < M;
            int sidx = 0;
            if (valid) sidx = (mode == 0) ? edges[2 * myrow] : edges[2 * myrow + 1];
            float* dstrow = g_pooled + (size_t)sidx * HID + pcol + wn * 64 + q * 4;
#pragma unroll
            for (int nf = 0; nf < 8; nf++) {
                float v0 = fmaxf(acc[mf][nf][0] + bb[nf][0], 0.f);
                float v1 = fmaxf(acc[mf][nf][1] + bb[nf][1], 0.f);
                float v2 = fmaxf(acc[mf][nf][2] + bb[nf][0], 0.f);
                float v3 = fmaxf(acc[mf][nf][3] + bb[nf][1], 0.f);
                float s0 = halfsel ? v0 : v2;
                float s1 = halfsel ? v1 : v3;
                float p0 = __shfl_xor_sync(0xffffffffu, s0, 1);
                float p1 = __shfl_xor_sync(0xffffffffu, s1, 1);
                float o0 = halfsel ? p0 : v0;
                float o1 = halfsel ? p1 : v1;
                float o2 = halfsel ? v2 : p0;
                float o3 = halfsel ? v3 : p1;
                if (valid) red_add_v4(dstrow + nf * 8, o0, o1, o2, o3);
            }
        }
    } else {
#pragma unroll
        for (int mf = 0; mf < MF; mf++)
#pragma unroll
            for (int half = 0; half < 2; half++) {
                int r = row0 + wm * (16 * MF) + mf * 16 + gr + half * 8;
                if (r >= M) continue;
                if (KIND == 0 || KIND == 2) {
                    __half* base = (KIND == 0) ? g_h : g_tp;
#pragma unroll
                    for (int nf = 0; nf < 8; nf++) {
                        int c = col0 + wn * 64 + nf * 8 + ct * 2;
                        float x = fmaxf(acc[mf][nf][half * 2 + 0] + bb[nf][0], 0.f);
                        float y = fmaxf(acc[mf][nf][half * 2 + 1] + bb[nf][1], 0.f);
                        *(__half2*)(base + packed_off(r, c)) = __floats2half2_rn(x, y);
                    }
                } else {  // KIND 3 or KIND 1 mode==1
                    int cbase = wn * 64 + ct * 2;
                    float* dst = out + (size_t)r * D_OUTK + cbase;
#pragma unroll
                    for (int nf = 0; nf < 8; nf++) {
                        float2 o;
                        o.x = fmaxf(acc[mf][nf][half * 2 + 0] + bb[nf][0], 0.f);
                        o.y = fmaxf(acc[mf][nf][half * 2 + 1] + bb[nf][1], 0.f);
                        *(float2*)(dst + nf * 8) = o;
                    }
                }
            }
    }
}

// ---------------------------------------------------------------------------
extern "C" void kernel_launch(void* const* d_in, const int* in_sizes, int n_in,
                              void* d_out, int out_size)
{
    const float* obj   = (const float*)d_in[0];
    const float* pred  = (const float*)d_in[1];
    const int*   edges = (const int*)  d_in[2];
    const float* W1 = (const float*)d_in[3];
    const float* b1 = (const float*)d_in[4];
    const float* W2 = (const float*)d_in[5];
    const float* b2 = (const float*)d_in[6];
    const float* W3 = (const float*)d_in[7];
    const float* b3 = (const float*)d_in[8];
    const float* W4 = (const float*)d_in[9];
    const float* b4 = (const float*)d_in[10];

    float* out     = (float*)d_out;
    float* out_obj = out;                           // (NOBJ, 128)
    float* out_p   = out + (size_t)NOBJ * D_OUTK;   // (NT, 128)

    cudaFuncSetAttribute((const void*)hgemm<0, 2>, cudaFuncAttributeMaxDynamicSharedMemorySize, SMEMB);
    cudaFuncSetAttribute((const void*)hgemm<1, 4>, cudaFuncAttributeMaxDynamicSharedMemorySize, SMEMB);
    cudaFuncSetAttribute((const void*)hgemm<2, 4>, cudaFuncAttributeMaxDynamicSharedMemorySize, SMEMB);
    cudaFuncSetAttribute((const void*)hgemm<3, 2>, cudaFuncAttributeMaxDynamicSharedMemorySize, SMEMB);

    zero_counts<<<(NOBJ + 255) / 256, 256>>>();
    prep_kernel<<<NB_TOTAL, 256>>>(obj, pred, edges, W1, W2, W3, W4);

    int gy_t = (NT + BM - 1) / BM;    // 1563
    int gy_o = (NOBJ + BM - 1) / BM;  // 782

    hgemm<0, 2><<<dim3(4, gy_t), 256, SMEMB>>>(edges, b1, nullptr, NT);
    hgemm<1, 4><<<dim3(9, gy_t), 128, SMEMB>>>(edges, b2, out_p, NT);
    normalize_h<<<(NOBJ * HID / 4 + 255) / 256, 256>>>();
    hgemm<2, 4><<<dim3(4, gy_o), 128, SMEMB>>>(edges, b3, nullptr, NOBJ);
    hgemm<3, 2><<<dim3(1, gy_o), 256, SMEMB>>>(edges, b4, out_obj, NOBJ);
}